// round 2
// baseline (speedup 1.0000x reference)
#include <cuda_runtime.h>
#include <math.h>

#define NN 100000
#define EE 1600000
#define FF 64
#define DEPTH 4

typedef unsigned long long u64;

// ------------------- scratch (device globals; no runtime allocs) -------------------
__device__ float g_P[(size_t)NN * 128];
__device__ float g_hbuf[2][(size_t)NN * 64];
__device__ float g_xbuf[2][(size_t)NN * 3];
__device__ float g_hacc[(size_t)NN * 64];     // h_neigh (written by gather, no zero needed)
__device__ float g_xacc[(size_t)NN * 3];
__device__ float g_t[(size_t)NN * 64];
__device__ float g_m[(size_t)EE * 64];        // per-edge messages
__device__ int   g_deg[NN];
__device__ int   g_off[NN + 1];
__device__ int   g_woff[NN];
__device__ int   g_bsum[256];
__device__ int   g_bscan[256];
__device__ int   g_eidx[EE];

// ------------------- helpers -------------------
__device__ __forceinline__ float silu_f(float v) {
    return __fdividef(v, 1.0f + __expf(-v));
}
__device__ __forceinline__ u64 pack2(float v) {
    u64 r; asm("mov.b64 %0, {%1, %1};" : "=l"(r) : "f"(v)); return r;
}
__device__ __forceinline__ void ffma2(u64 &d, u64 a, u64 b) {
    asm("fma.rn.f32x2 %0, %1, %2, %3;" : "=l"(d) : "l"(a), "l"(b), "l"(d));
}
__device__ __forceinline__ void unpack2(u64 v, float &lo, float &hi) {
    asm("mov.b64 {%0, %1}, %2;" : "=f"(lo), "=f"(hi) : "l"(v));
}
__device__ __forceinline__ void red1(float* p, float a) {
    asm volatile("red.global.add.f32 [%0], %1;" :: "l"(p), "f"(a) : "memory");
}

// ------------------- CSR build (once per call) -------------------
__global__ void deg_zero_kernel(int* __restrict__ deg, float* __restrict__ xacc, int n) {
    int i = blockIdx.x * blockDim.x + threadIdx.x;
    if (i < n) deg[i] = 0;
    if (i < n * 3) xacc[i] = 0.f;   // n*3 <= grid covers? grid sized for n*3
}
__global__ void deg_count_kernel(const int* __restrict__ dst, int* __restrict__ deg, int E) {
    int e = blockIdx.x * blockDim.x + threadIdx.x;
    if (e < E) atomicAdd(&deg[dst[e]], 1);
}
__global__ void scan_blocks_kernel(const int* __restrict__ deg, int* __restrict__ off,
                                   int* __restrict__ bsum, int n) {
    __shared__ int s[512];
    int tid = threadIdx.x;
    int i = blockIdx.x * 512 + tid;
    int v = (i < n) ? deg[i] : 0;
    s[tid] = v;
    __syncthreads();
    for (int d = 1; d < 512; d <<= 1) {
        int t2 = (tid >= d) ? s[tid - d] : 0;
        __syncthreads();
        s[tid] += t2;
        __syncthreads();
    }
    if (i < n) off[i] = s[tid] - v;       // exclusive
    if (tid == 511) bsum[blockIdx.x] = s[511];
}
__global__ void scan_bsums_kernel(const int* __restrict__ bsum, int* __restrict__ bscan, int nb) {
    if (threadIdx.x == 0 && blockIdx.x == 0) {
        int acc = 0;
        for (int b = 0; b < nb; b++) { bscan[b] = acc; acc += bsum[b]; }
    }
}
__global__ void scan_add_kernel(int* __restrict__ off, const int* __restrict__ bscan,
                                int* __restrict__ woff, int n, int Etot) {
    int i = blockIdx.x * blockDim.x + threadIdx.x;
    if (i < n) {
        int v = off[i] + bscan[i >> 9];
        off[i] = v;
        woff[i] = v;
    }
    if (i == 0) off[n] = Etot;
}
__global__ void fill_eidx_kernel(const int* __restrict__ dst, int* __restrict__ woff,
                                 int* __restrict__ eidx, int E) {
    int e = blockIdx.x * blockDim.x + threadIdx.x;
    if (e < E) {
        int p = atomicAdd(&woff[dst[e]], 1);
        eidx[p] = e;
    }
}

// ------------------- zero xacc per layer -------------------
__global__ void zerox_kernel(float* __restrict__ xacc, int n3) {
    int i = blockIdx.x * blockDim.x + threadIdx.x;
    if (i < n3) xacc[i] = 0.f;
}

// ------------------- P = h @ [Wa | Wb] -------------------
__global__ __launch_bounds__(256) void gemm_P_kernel(
    const float* __restrict__ h, const float* __restrict__ ew1,
    float* __restrict__ P, int n)
{
    extern __shared__ float sm[];
    float* As = sm;              // 64 x 64
    float* Ws = sm + 64 * 64;    // 64 x 128
    int t = threadIdx.x;
    int row0 = blockIdx.x * 64;

    for (int i = t; i < 64 * 64; i += 256) {
        int r = i >> 6, c = i & 63;
        int gr = row0 + r;
        As[i] = (gr < n) ? h[(size_t)gr * 64 + c] : 0.f;
    }
    for (int i = t; i < 64 * 128; i += 256) {
        int k = i >> 7, j = i & 127;
        Ws[i] = (j < 64) ? ew1[k * 64 + j] : ew1[(64 + k) * 64 + (j - 64)];
    }
    __syncthreads();

    int tx = t & 31;
    int ty = t >> 5;
    float acc[8][4];
#pragma unroll
    for (int i = 0; i < 8; i++) { acc[i][0]=0.f; acc[i][1]=0.f; acc[i][2]=0.f; acc[i][3]=0.f; }

    const float4* Wq = (const float4*)Ws;
#pragma unroll 8
    for (int k = 0; k < 64; k++) {
        float4 w = Wq[k * 32 + tx];
#pragma unroll
        for (int i = 0; i < 8; i++) {
            float av = As[(ty * 8 + i) * 64 + k];
            acc[i][0] += av * w.x; acc[i][1] += av * w.y;
            acc[i][2] += av * w.z; acc[i][3] += av * w.w;
        }
    }
#pragma unroll
    for (int i = 0; i < 8; i++) {
        int row = row0 + ty * 8 + i;
        if (row < n) {
            float4 o = make_float4(acc[i][0], acc[i][1], acc[i][2], acc[i][3]);
            ((float4*)P)[(size_t)row * 32 + tx] = o;
        }
    }
}

// ------------------- edge kernel -------------------
// dynamic smem layout (floats): [0,4096) ew2 | [4096,8192) cw1 | [8192,16384) stage[64][128]
// | [16384,16448) wr | +64 eb1 | +64 eb2 | +64 cb1 | +64 cw2
template<bool STORE>
__global__ __launch_bounds__(128, 3) void edge_kernel(
    const int* __restrict__ src, const int* __restrict__ dst,
    const float* __restrict__ x, const float* __restrict__ P,
    const float* __restrict__ wr,  const float* __restrict__ eb1,
    const float* __restrict__ ew2, const float* __restrict__ eb2,
    const float* __restrict__ cw1, const float* __restrict__ cb1,
    const float* __restrict__ cw2,
    float* __restrict__ mbuf, float* __restrict__ xacc, int E)
{
    extern __shared__ float sm[];
    float* s_w2   = sm;
    float* s_c1   = sm + 4096;
    float* s_stage= sm + 8192;
    float* s_wr   = sm + 16384;
    float* s_eb1  = sm + 16448;
    float* s_eb2  = sm + 16512;
    float* s_cb1  = sm + 16576;
    float* s_cw2  = sm + 16640;

    int t = threadIdx.x;
    for (int i = t; i < 4096; i += 128) { s_w2[i] = ew2[i]; s_c1[i] = cw1[i]; }
    if (t < 64) {
        s_wr[t] = wr[t]; s_eb1[t] = eb1[t]; s_eb2[t] = eb2[t];
        s_cb1[t] = cb1[t]; s_cw2[t] = cw2[t];
    }
    __syncthreads();

    int e = blockIdx.x * 128 + t;
    if (e >= E) return;

    int si = src[e], di = dst[e];

    float dx0 = x[si * 3 + 0] - x[di * 3 + 0];
    float dx1 = x[si * 3 + 1] - x[di * 3 + 1];
    float dx2 = x[si * 3 + 2] - x[di * 3 + 2];
    float r = dx0 * dx0 + dx1 * dx1 + dx2 * dx2;
    float inv = __fdividef(1.0f, sqrtf(r) + 1e-30f);
    float u0 = dx0 * inv, u1 = dx1 * inv, u2 = dx2 * inv;

    // m1 = silu(P[src][0:64] + P[dst][64:128] + r*wr + eb1) -> stage
    {
        const float4* Pa = (const float4*)(P + (size_t)si * 128);
        const float4* Pb = (const float4*)(P + (size_t)di * 128 + 64);
#pragma unroll
        for (int i = 0; i < 16; i++) {
            float4 va = Pa[i], vb = Pb[i];
            float v0 = silu_f(va.x + vb.x + r * s_wr[4*i+0] + s_eb1[4*i+0]);
            float v1 = silu_f(va.y + vb.y + r * s_wr[4*i+1] + s_eb1[4*i+1]);
            float v2 = silu_f(va.z + vb.z + r * s_wr[4*i+2] + s_eb1[4*i+2]);
            float v3 = silu_f(va.w + vb.w + r * s_wr[4*i+3] + s_eb1[4*i+3]);
            s_stage[(4*i+0)*128 + t] = v0;
            s_stage[(4*i+1)*128 + t] = v1;
            s_stage[(4*i+2)*128 + t] = v2;
            s_stage[(4*i+3)*128 + t] = v3;
        }
    }

    u64 acc[32];

    // ---- GEMM1: m = silu(m1 @ ew2 + eb2) ----
    {
        const u64* bq = (const u64*)s_eb2;
#pragma unroll
        for (int j = 0; j < 32; j++) acc[j] = bq[j];
        const ulonglong2* wq = (const ulonglong2*)s_w2;
#pragma unroll
        for (int k = 0; k < 64; k++) {
            u64 ak = pack2(s_stage[k*128 + t]);
#pragma unroll
            for (int j = 0; j < 16; j++) {
                ulonglong2 w = wq[k * 16 + j];
                ffma2(acc[2*j+0], ak, w.x);
                ffma2(acc[2*j+1], ak, w.y);
            }
        }
        // silu, write m to stage (own column only, no sync needed) and to gmem
        float* mrow = mbuf + (size_t)e * 64;
#pragma unroll
        for (int j = 0; j < 16; j++) {
            float a0, a1, a2, a3;
            unpack2(acc[2*j+0], a0, a1);
            unpack2(acc[2*j+1], a2, a3);
            a0 = silu_f(a0); a1 = silu_f(a1); a2 = silu_f(a2); a3 = silu_f(a3);
            s_stage[(4*j+0)*128 + t] = a0;
            s_stage[(4*j+1)*128 + t] = a1;
            s_stage[(4*j+2)*128 + t] = a2;
            s_stage[(4*j+3)*128 + t] = a3;
            if (STORE) {
                float4 o = make_float4(a0, a1, a2, a3);
                ((float4*)mrow)[j] = o;
            }
        }
    }

    // ---- GEMM2: c = silu(m @ cw1 + cb1) . cw2 ----
    float c;
    {
        const u64* bq = (const u64*)s_cb1;
#pragma unroll
        for (int j = 0; j < 32; j++) acc[j] = bq[j];
        const ulonglong2* wq = (const ulonglong2*)s_c1;
#pragma unroll
        for (int k = 0; k < 64; k++) {
            u64 ak = pack2(s_stage[k*128 + t]);
#pragma unroll
            for (int j = 0; j < 16; j++) {
                ulonglong2 w = wq[k * 16 + j];
                ffma2(acc[2*j+0], ak, w.x);
                ffma2(acc[2*j+1], ak, w.y);
            }
        }
        c = 0.f;
#pragma unroll
        for (int j = 0; j < 32; j++) {
            float lo, hi; unpack2(acc[j], lo, hi);
            c += silu_f(lo) * s_cw2[2*j+0];
            c += silu_f(hi) * s_cw2[2*j+1];
        }
    }

    float* xp = xacc + (size_t)di * 3;
    red1(xp + 0, c * u0);
    red1(xp + 1, c * u1);
    red1(xp + 2, c * u2);
}

// ------------------- gather: h_neigh[n] = sum of m over in-edges -------------------
__global__ void gather_kernel(const float* __restrict__ m, const int* __restrict__ off,
                              const int* __restrict__ eidx, float* __restrict__ hn, int n)
{
    int warp = (blockIdx.x * blockDim.x + threadIdx.x) >> 5;
    int lane = threadIdx.x & 31;
    if (warp >= n) return;
    int b = off[warp], en = off[warp + 1];
    float ax = 0.f, ay = 0.f;
    for (int i = b; i < en; i++) {
        int eid = eidx[i];
        float2 v = ((const float2*)(m + (size_t)eid * 64))[lane];
        ax += v.x; ay += v.y;
    }
    float2 o; o.x = ax; o.y = ay;
    ((float2*)(hn + (size_t)warp * 64))[lane] = o;
}

// ------------------- node GEMM -------------------
template<int K, bool ACT>
__global__ __launch_bounds__(256) void node_gemm_kernel(
    const float* __restrict__ A1, const float* __restrict__ A2,
    const float* __restrict__ W, const float* __restrict__ bias,
    float* __restrict__ out, int n)
{
    extern __shared__ float sm[];
    float* As = sm;
    float* Ws = sm + 64 * K;
    int t = threadIdx.x;
    int row0 = blockIdx.x * 64;

    for (int i = t; i < 64 * K; i += 256) {
        int r = i / K, c = i % K;
        int gr = row0 + r;
        float v = 0.f;
        if (gr < n) {
            if (K == 64 || c < 64) v = A1[(size_t)gr * 64 + (c & 63)];
            else                   v = A2[(size_t)gr * 64 + (c - 64)];
        }
        As[i] = v;
    }
    for (int i = t; i < K * 64; i += 256) Ws[i] = W[i];
    __syncthreads();

    int tx = t & 15;
    int ty = t >> 4;
    float acc[4][4];
#pragma unroll
    for (int i = 0; i < 4; i++) { acc[i][0]=0.f; acc[i][1]=0.f; acc[i][2]=0.f; acc[i][3]=0.f; }

    const float4* Wq = (const float4*)Ws;
#pragma unroll 8
    for (int k = 0; k < K; k++) {
        float4 w = Wq[k * 16 + tx];
#pragma unroll
        for (int i = 0; i < 4; i++) {
            float av = As[(ty * 4 + i) * K + k];
            acc[i][0] += av * w.x; acc[i][1] += av * w.y;
            acc[i][2] += av * w.z; acc[i][3] += av * w.w;
        }
    }

    float b0 = bias[tx*4+0], b1 = bias[tx*4+1], b2 = bias[tx*4+2], b3 = bias[tx*4+3];
#pragma unroll
    for (int i = 0; i < 4; i++) {
        int row = row0 + ty * 4 + i;
        if (row < n) {
            float4 o;
            o.x = acc[i][0] + b0; o.y = acc[i][1] + b1;
            o.z = acc[i][2] + b2; o.w = acc[i][3] + b3;
            if (ACT) { o.x = silu_f(o.x); o.y = silu_f(o.y); o.z = silu_f(o.z); o.w = silu_f(o.w); }
            ((float4*)out)[(size_t)row * 16 + tx] = o;
        }
    }
}

// ------------------- x update -------------------
__global__ void xupd_kernel(const float* __restrict__ x, const float* __restrict__ xacc,
                            float* __restrict__ out, int n3)
{
    int i = blockIdx.x * blockDim.x + threadIdx.x;
    if (i < n3) out[i] = x[i] + xacc[i];
}

// ------------------- launch -------------------
extern "C" void kernel_launch(void* const* d_in, const int* in_sizes, int n_in,
                              void* d_out, int out_size)
{
    const float* h0  = (const float*)d_in[0];
    const float* x0  = (const float*)d_in[1];
    const int*   src = (const int*)d_in[2];
    const int*   dst = (const int*)d_in[3];
    const float* ew1 = (const float*)d_in[4];
    const float* eb1 = (const float*)d_in[5];
    const float* ew2 = (const float*)d_in[6];
    const float* eb2 = (const float*)d_in[7];
    const float* nw1 = (const float*)d_in[8];
    const float* nb1 = (const float*)d_in[9];
    const float* nw2 = (const float*)d_in[10];
    const float* nb2 = (const float*)d_in[11];
    const float* cw1 = (const float*)d_in[12];
    const float* cb1 = (const float*)d_in[13];
    const float* cw2 = (const float*)d_in[14];

    int n = in_sizes[0] / 64;
    int E = in_sizes[2];

    float *P, *hA, *xA, *hacc, *xacc, *tb, *mbuf;
    int *deg, *off, *woff, *bsum, *bscan, *eidx;
    cudaGetSymbolAddress((void**)&P,    g_P);
    cudaGetSymbolAddress((void**)&hA,   g_hbuf);
    cudaGetSymbolAddress((void**)&xA,   g_xbuf);
    cudaGetSymbolAddress((void**)&hacc, g_hacc);
    cudaGetSymbolAddress((void**)&xacc, g_xacc);
    cudaGetSymbolAddress((void**)&tb,   g_t);
    cudaGetSymbolAddress((void**)&mbuf, g_m);
    cudaGetSymbolAddress((void**)&deg,  g_deg);
    cudaGetSymbolAddress((void**)&off,  g_off);
    cudaGetSymbolAddress((void**)&woff, g_woff);
    cudaGetSymbolAddress((void**)&bsum, g_bsum);
    cudaGetSymbolAddress((void**)&bscan,g_bscan);
    cudaGetSymbolAddress((void**)&eidx, g_eidx);

    float* hb[2] = { hA, hA + (size_t)NN * 64 };
    float* xb[2] = { xA, xA + (size_t)NN * 3 };

    const int smP  = (64*64 + 64*128) * 4;
    const int smE  = (4096 + 4096 + 8192 + 5*64 + 16) * 4;
    const int smN1 = (64*128 + 128*64) * 4;
    const int smN2 = (64*64 + 64*64) * 4;
    cudaFuncSetAttribute(gemm_P_kernel, cudaFuncAttributeMaxDynamicSharedMemorySize, smP);
    cudaFuncSetAttribute(edge_kernel<true>,  cudaFuncAttributeMaxDynamicSharedMemorySize, smE);
    cudaFuncSetAttribute(edge_kernel<false>, cudaFuncAttributeMaxDynamicSharedMemorySize, smE);
    cudaFuncSetAttribute(node_gemm_kernel<128, true>,  cudaFuncAttributeMaxDynamicSharedMemorySize, smN1);
    cudaFuncSetAttribute(node_gemm_kernel<64, false>,  cudaFuncAttributeMaxDynamicSharedMemorySize, smN2);

    int nb_rows = (n + 63) / 64;
    int eb_blocks = (E + 127) / 128;
    int scan_nb = (n + 511) / 512;

    // ---- CSR build (graph is static across layers) ----
    deg_zero_kernel<<<(n * 3 + 255) / 256, 256>>>(deg, xacc, n);
    deg_count_kernel<<<(E + 255) / 256, 256>>>(dst, deg, E);
    scan_blocks_kernel<<<scan_nb, 512>>>(deg, off, bsum, n);
    scan_bsums_kernel<<<1, 32>>>(bsum, bscan, scan_nb);
    scan_add_kernel<<<(n + 255) / 256, 256>>>(off, bscan, woff, n, E);
    fill_eidx_kernel<<<(E + 255) / 256, 256>>>(dst, woff, eidx, E);

    for (int d = 0; d < DEPTH; d++) {
        const float* hc = d ? hb[(d - 1) & 1] : h0;
        const float* xc = d ? xb[(d - 1) & 1] : x0;
        float* xo = (d == DEPTH - 1) ? (float*)d_out : xb[d & 1];

        if (d) zerox_kernel<<<(n * 3 + 255) / 256, 256>>>(xacc, n * 3);

        gemm_P_kernel<<<nb_rows, 256, smP>>>(hc, ew1 + (size_t)d * 129 * 64, P, n);

        if (d < DEPTH - 1) {
            edge_kernel<true><<<eb_blocks, 128, smE>>>(
                src, dst, xc, P,
                ew1 + (size_t)d * 129 * 64 + 128 * 64, eb1 + d * 64,
                ew2 + (size_t)d * 4096, eb2 + d * 64,
                cw1 + (size_t)d * 4096, cb1 + d * 64, cw2 + d * 64,
                mbuf, xacc, E);

            gather_kernel<<<(n * 32 + 255) / 256, 256>>>(mbuf, off, eidx, hacc, n);

            node_gemm_kernel<128, true><<<nb_rows, 256, smN1>>>(
                hc, hacc, nw1 + (size_t)d * 128 * 64, nb1 + d * 64, tb, n);
            node_gemm_kernel<64, false><<<nb_rows, 256, smN2>>>(
                tb, tb, nw2 + (size_t)d * 4096, nb2 + d * 64, hb[d & 1], n);
        } else {
            edge_kernel<false><<<eb_blocks, 128, smE>>>(
                src, dst, xc, P,
                ew1 + (size_t)d * 129 * 64 + 128 * 64, eb1 + d * 64,
                ew2 + (size_t)d * 4096, eb2 + d * 64,
                cw1 + (size_t)d * 4096, cb1 + d * 64, cw2 + d * 64,
                mbuf, xacc, E);
        }

        xupd_kernel<<<(n * 3 + 255) / 256, 256>>>(xc, xacc, xo, n * 3);
    }
}

// round 4
// speedup vs baseline: 1.0278x; 1.0278x over previous
#include <cuda_runtime.h>
#include <math.h>

#define NN 100000
#define EE 1600000
#define DEPTH 4

typedef unsigned long long u64;

// ------------------- scratch (device globals; no runtime allocs) -------------------
__device__ float g_P[(size_t)NN * 128];
__device__ float g_hbuf[2][(size_t)NN * 64];
__device__ float g_xbuf[2][(size_t)NN * 3];
__device__ float g_hacc[(size_t)NN * 64];
__device__ float g_xacc[(size_t)NN * 3];
__device__ float g_t[(size_t)NN * 64];
__device__ float g_m[(size_t)EE * 64];
__device__ int   g_deg[NN];
__device__ int   g_off[NN + 1];
__device__ int   g_woff[NN];
__device__ int   g_bsum[256];
__device__ int   g_bscan[256];
__device__ int   g_eidx[EE];

// ------------------- helpers -------------------
__device__ __forceinline__ float silu_f(float v) {
    return __fdividef(v, 1.0f + __expf(-v));
}
__device__ __forceinline__ u64 pack2(float v) {
    u64 r; asm("mov.b64 %0, {%1, %1};" : "=l"(r) : "f"(v)); return r;
}
__device__ __forceinline__ void ffma2(u64 &d, u64 a, u64 b) {
    asm("fma.rn.f32x2 %0, %1, %2, %3;" : "=l"(d) : "l"(a), "l"(b), "l"(d));
}
__device__ __forceinline__ void unpack2(u64 v, float &lo, float &hi) {
    asm("mov.b64 {%0, %1}, %2;" : "=f"(lo), "=f"(hi) : "l"(v));
}
__device__ __forceinline__ void red1(float* p, float a) {
    asm volatile("red.global.add.f32 [%0], %1;" :: "l"(p), "f"(a) : "memory");
}

// ------------------- CSR build -------------------
__global__ void deg_zero_kernel(int* __restrict__ deg, float* __restrict__ xacc, int n) {
    int i = blockIdx.x * blockDim.x + threadIdx.x;
    if (i < n) deg[i] = 0;
    if (i < n * 3) xacc[i] = 0.f;
}
__global__ void deg_count_kernel(const int* __restrict__ dst, int* __restrict__ deg, int E) {
    int e = blockIdx.x * blockDim.x + threadIdx.x;
    if (e < E) atomicAdd(&deg[dst[e]], 1);
}
__global__ void scan_blocks_kernel(const int* __restrict__ deg, int* __restrict__ off,
                                   int* __restrict__ bsum, int n) {
    __shared__ int s[512];
    int tid = threadIdx.x;
    int i = blockIdx.x * 512 + tid;
    int v = (i < n) ? deg[i] : 0;
    s[tid] = v;
    __syncthreads();
    for (int d = 1; d < 512; d <<= 1) {
        int t2 = (tid >= d) ? s[tid - d] : 0;
        __syncthreads();
        s[tid] += t2;
        __syncthreads();
    }
    if (i < n) off[i] = s[tid] - v;
    if (tid == 511) bsum[blockIdx.x] = s[511];
}
__global__ void scan_bsums_kernel(const int* __restrict__ bsum, int* __restrict__ bscan, int nb) {
    if (threadIdx.x == 0 && blockIdx.x == 0) {
        int acc = 0;
        for (int b = 0; b < nb; b++) { bscan[b] = acc; acc += bsum[b]; }
    }
}
__global__ void scan_add_kernel(int* __restrict__ off, const int* __restrict__ bscan,
                                int* __restrict__ woff, int n, int Etot) {
    int i = blockIdx.x * blockDim.x + threadIdx.x;
    if (i < n) {
        int v = off[i] + bscan[i >> 9];
        off[i] = v;
        woff[i] = v;
    }
    if (i == 0) off[n] = Etot;
}
__global__ void fill_eidx_kernel(const int* __restrict__ dst, int* __restrict__ woff,
                                 int* __restrict__ eidx, int E) {
    int e = blockIdx.x * blockDim.x + threadIdx.x;
    if (e < E) {
        int p = atomicAdd(&woff[dst[e]], 1);
        eidx[p] = e;
    }
}
__global__ void zerox_kernel(float* __restrict__ xacc, int n3) {
    int i = blockIdx.x * blockDim.x + threadIdx.x;
    if (i < n3) xacc[i] = 0.f;
}

// ------------------- P = h @ [Wa | Wb] -------------------
__global__ __launch_bounds__(256) void gemm_P_kernel(
    const float* __restrict__ h, const float* __restrict__ ew1,
    float* __restrict__ P, int n)
{
    extern __shared__ float sm[];
    float* As = sm;              // 64 x 64
    float* Ws = sm + 64 * 64;    // 64 x 128
    int t = threadIdx.x;
    int row0 = blockIdx.x * 64;

    for (int i = t; i < 64 * 64; i += 256) {
        int r = i >> 6, c = i & 63;
        int gr = row0 + r;
        As[i] = (gr < n) ? h[(size_t)gr * 64 + c] : 0.f;
    }
    for (int i = t; i < 64 * 128; i += 256) {
        int k = i >> 7, j = i & 127;
        Ws[i] = (j < 64) ? ew1[k * 64 + j] : ew1[(64 + k) * 64 + (j - 64)];
    }
    __syncthreads();

    int tx = t & 31;
    int ty = t >> 5;
    float acc[8][4];
#pragma unroll
    for (int i = 0; i < 8; i++) { acc[i][0]=0.f; acc[i][1]=0.f; acc[i][2]=0.f; acc[i][3]=0.f; }

    const float4* Wq = (const float4*)Ws;
#pragma unroll 8
    for (int k = 0; k < 64; k++) {
        float4 w = Wq[k * 32 + tx];
#pragma unroll
        for (int i = 0; i < 8; i++) {
            float av = As[(ty * 8 + i) * 64 + k];
            acc[i][0] += av * w.x; acc[i][1] += av * w.y;
            acc[i][2] += av * w.z; acc[i][3] += av * w.w;
        }
    }
#pragma unroll
    for (int i = 0; i < 8; i++) {
        int row = row0 + ty * 8 + i;
        if (row < n) {
            float4 o = make_float4(acc[i][0], acc[i][1], acc[i][2], acc[i][3]);
            ((float4*)P)[(size_t)row * 32 + tx] = o;
        }
    }
}

// ------------------- edge kernel: block-tiled GEMM, 128 edges/block -------------------
#define STG_LD 68
template<bool STORE>
__global__ __launch_bounds__(256, 3) void edge_kernel(
    const int* __restrict__ src, const int* __restrict__ dst,
    const float* __restrict__ x, const float* __restrict__ P,
    const float* __restrict__ wr,  const float* __restrict__ eb1,
    const float* __restrict__ ew2, const float* __restrict__ eb2,
    const float* __restrict__ cw1, const float* __restrict__ cb1,
    const float* __restrict__ cw2,
    float* __restrict__ mbuf, float* __restrict__ xacc, int E)
{
    extern __shared__ float sm[];
    float* s_stage = sm;                      // 128*68 = 8704
    float* s_w     = sm + 8704;               // 4096
    float* s_u0    = sm + 12800;
    float* s_u1    = sm + 12928;
    float* s_u2    = sm + 13056;
    float* s_cpart = sm + 13184;
    int*   s_di    = (int*)(sm + 13312);
    float* s_wr    = sm + 13440;
    float* s_eb1   = sm + 13504;
    float* s_eb2   = sm + 13568;
    float* s_cb1   = sm + 13632;
    float* s_cw2   = sm + 13696;

    int t = threadIdx.x;
    int em0 = blockIdx.x * 128;

    // load w2 + small arrays
    {
        float4* wd = (float4*)s_w;
        const float4* ws = (const float4*)ew2;
#pragma unroll
        for (int i = 0; i < 4; i++) wd[t + 256 * i] = ws[t + 256 * i];
        if (t < 64) {
            s_wr[t] = wr[t]; s_eb1[t] = eb1[t]; s_eb2[t] = eb2[t];
            s_cb1[t] = cb1[t]; s_cw2[t] = cw2[t];
        }
    }
    __syncthreads();   // <<< FIX: s_wr/s_eb1 written by t<64, read by all below

    // ---- m1 stage: thread handles edge (t>>1), half (t&1) ----
    {
        int eloc = t >> 1, half = t & 1;
        int e = em0 + eloc;
        int si = 0, di = 0;
        float r = 0.f, u0 = 0.f, u1 = 0.f, u2 = 0.f;
        if (e < E) {
            si = src[e]; di = dst[e];
            float dx0 = x[si * 3 + 0] - x[di * 3 + 0];
            float dx1 = x[si * 3 + 1] - x[di * 3 + 1];
            float dx2 = x[si * 3 + 2] - x[di * 3 + 2];
            r = dx0 * dx0 + dx1 * dx1 + dx2 * dx2;
            float inv = __fdividef(1.0f, sqrtf(r) + 1e-30f);
            u0 = dx0 * inv; u1 = dx1 * inv; u2 = dx2 * inv;
        }
        if (half == 0) {
            s_di[eloc] = di;
            s_u0[eloc] = u0; s_u1[eloc] = u1; s_u2[eloc] = u2;
        }
        const float4* Pa = (const float4*)(P + (size_t)si * 128) + half * 8;
        const float4* Pb = (const float4*)(P + (size_t)di * 128 + 64) + half * 8;
        float4* srow = (float4*)(s_stage + eloc * STG_LD + half * 32);
#pragma unroll
        for (int i = 0; i < 8; i++) {
            float4 va = Pa[i], vb = Pb[i];
            int f = half * 32 + 4 * i;
            float4 o;
            o.x = silu_f(va.x + vb.x + r * s_wr[f+0] + s_eb1[f+0]);
            o.y = silu_f(va.y + vb.y + r * s_wr[f+1] + s_eb1[f+1]);
            o.z = silu_f(va.z + vb.z + r * s_wr[f+2] + s_eb1[f+2]);
            o.w = silu_f(va.w + vb.w + r * s_wr[f+3] + s_eb1[f+3]);
            srow[i] = o;
        }
    }
    __syncthreads();

    int tx = t & 7;          // feature group: feats tx*8 .. tx*8+7
    int te = t >> 3;         // edge group: edges te*4 .. te*4+3
    const float* arow = s_stage + te * 4 * STG_LD;
    const ulonglong2* wq = (const ulonglong2*)s_w;

    u64 acc[4][4];

    // ---- GEMM1: m = silu(m1 @ ew2 + eb2) ----
    {
        const u64* bq = (const u64*)(s_eb2 + tx * 8);
#pragma unroll
        for (int e2 = 0; e2 < 4; e2++) {
            acc[e2][0] = bq[0]; acc[e2][1] = bq[1]; acc[e2][2] = bq[2]; acc[e2][3] = bq[3];
        }
#pragma unroll 8
        for (int k = 0; k < 64; k++) {
            float a0 = arow[0*STG_LD + k], a1 = arow[1*STG_LD + k];
            float a2 = arow[2*STG_LD + k], a3 = arow[3*STG_LD + k];
            ulonglong2 w01 = wq[k * 16 + tx * 2];
            ulonglong2 w23 = wq[k * 16 + tx * 2 + 1];
            u64 p;
            p = pack2(a0); ffma2(acc[0][0],p,w01.x); ffma2(acc[0][1],p,w01.y); ffma2(acc[0][2],p,w23.x); ffma2(acc[0][3],p,w23.y);
            p = pack2(a1); ffma2(acc[1][0],p,w01.x); ffma2(acc[1][1],p,w01.y); ffma2(acc[1][2],p,w23.x); ffma2(acc[1][3],p,w23.y);
            p = pack2(a2); ffma2(acc[2][0],p,w01.x); ffma2(acc[2][1],p,w01.y); ffma2(acc[2][2],p,w23.x); ffma2(acc[2][3],p,w23.y);
            p = pack2(a3); ffma2(acc[3][0],p,w01.x); ffma2(acc[3][1],p,w01.y); ffma2(acc[3][2],p,w23.x); ffma2(acc[3][3],p,w23.y);
        }
    }
    __syncthreads();   // everyone done reading stage + w2

    // epilogue: silu, write stage rows + gmem m; reload cw1 into s_w
    {
        float4* wd = (float4*)s_w;
        const float4* ws = (const float4*)cw1;
#pragma unroll
        for (int i = 0; i < 4; i++) wd[t + 256 * i] = ws[t + 256 * i];
    }
#pragma unroll
    for (int e2 = 0; e2 < 4; e2++) {
        float f0,f1,f2,f3,f4,f5,f6,f7;
        unpack2(acc[e2][0], f0, f1); unpack2(acc[e2][1], f2, f3);
        unpack2(acc[e2][2], f4, f5); unpack2(acc[e2][3], f6, f7);
        f0=silu_f(f0); f1=silu_f(f1); f2=silu_f(f2); f3=silu_f(f3);
        f4=silu_f(f4); f5=silu_f(f5); f6=silu_f(f6); f7=silu_f(f7);
        int eloc = te * 4 + e2;
        float4* srow = (float4*)(s_stage + eloc * STG_LD + tx * 8);
        srow[0] = make_float4(f0,f1,f2,f3);
        srow[1] = make_float4(f4,f5,f6,f7);
        if (STORE) {
            int e = em0 + eloc;
            if (e < E) {
                float4* mrow = (float4*)(mbuf + (size_t)e * 64 + tx * 8);
                mrow[0] = make_float4(f0,f1,f2,f3);
                mrow[1] = make_float4(f4,f5,f6,f7);
            }
        }
    }
    __syncthreads();

    // ---- GEMM2: c1 = silu(m @ cw1 + cb1) ----
    {
        const u64* bq = (const u64*)(s_cb1 + tx * 8);
#pragma unroll
        for (int e2 = 0; e2 < 4; e2++) {
            acc[e2][0] = bq[0]; acc[e2][1] = bq[1]; acc[e2][2] = bq[2]; acc[e2][3] = bq[3];
        }
#pragma unroll 8
        for (int k = 0; k < 64; k++) {
            float a0 = arow[0*STG_LD + k], a1 = arow[1*STG_LD + k];
            float a2 = arow[2*STG_LD + k], a3 = arow[3*STG_LD + k];
            ulonglong2 w01 = wq[k * 16 + tx * 2];
            ulonglong2 w23 = wq[k * 16 + tx * 2 + 1];
            u64 p;
            p = pack2(a0); ffma2(acc[0][0],p,w01.x); ffma2(acc[0][1],p,w01.y); ffma2(acc[0][2],p,w23.x); ffma2(acc[0][3],p,w23.y);
            p = pack2(a1); ffma2(acc[1][0],p,w01.x); ffma2(acc[1][1],p,w01.y); ffma2(acc[1][2],p,w23.x); ffma2(acc[1][3],p,w23.y);
            p = pack2(a2); ffma2(acc[2][0],p,w01.x); ffma2(acc[2][1],p,w01.y); ffma2(acc[2][2],p,w23.x); ffma2(acc[2][3],p,w23.y);
            p = pack2(a3); ffma2(acc[3][0],p,w01.x); ffma2(acc[3][1],p,w01.y); ffma2(acc[3][2],p,w23.x); ffma2(acc[3][3],p,w23.y);
        }
    }

    // per-edge dot with cw2, reduce over the 8 feature-group lanes
    float c0 = s_cw2[tx*8+0], c1 = s_cw2[tx*8+1], c2 = s_cw2[tx*8+2], c3 = s_cw2[tx*8+3];
    float c4 = s_cw2[tx*8+4], c5 = s_cw2[tx*8+5], c6 = s_cw2[tx*8+6], c7 = s_cw2[tx*8+7];
#pragma unroll
    for (int e2 = 0; e2 < 4; e2++) {
        float f0,f1,f2,f3,f4,f5,f6,f7;
        unpack2(acc[e2][0], f0, f1); unpack2(acc[e2][1], f2, f3);
        unpack2(acc[e2][2], f4, f5); unpack2(acc[e2][3], f6, f7);
        float p = silu_f(f0)*c0 + silu_f(f1)*c1 + silu_f(f2)*c2 + silu_f(f3)*c3
                + silu_f(f4)*c4 + silu_f(f5)*c5 + silu_f(f6)*c6 + silu_f(f7)*c7;
        p += __shfl_down_sync(0xffffffffu, p, 4, 8);
        p += __shfl_down_sync(0xffffffffu, p, 2, 8);
        p += __shfl_down_sync(0xffffffffu, p, 1, 8);
        if (tx == 0) s_cpart[te * 4 + e2] = p;
    }
    __syncthreads();

    if (t < 128) {
        int e = em0 + t;
        if (e < E) {
            float c = s_cpart[t];
            int di = s_di[t];
            float* xp = xacc + (size_t)di * 3;
            red1(xp + 0, c * s_u0[t]);
            red1(xp + 1, c * s_u1[t]);
            red1(xp + 2, c * s_u2[t]);
        }
    }
}

// ------------------- gather -------------------
__global__ void gather_kernel(const float* __restrict__ m, const int* __restrict__ off,
                              const int* __restrict__ eidx, float* __restrict__ hn, int n)
{
    int warp = (blockIdx.x * blockDim.x + threadIdx.x) >> 5;
    int lane = threadIdx.x & 31;
    if (warp >= n) return;
    int b = off[warp], en = off[warp + 1];
    float ax = 0.f, ay = 0.f;
    for (int i = b; i < en; i++) {
        int eid = eidx[i];
        float2 v = ((const float2*)(m + (size_t)eid * 64))[lane];
        ax += v.x; ay += v.y;
    }
    float2 o; o.x = ax; o.y = ay;
    ((float2*)(hn + (size_t)warp * 64))[lane] = o;
}

// ------------------- node GEMM -------------------
template<int K, bool ACT>
__global__ __launch_bounds__(256) void node_gemm_kernel(
    const float* __restrict__ A1, const float* __restrict__ A2,
    const float* __restrict__ W, const float* __restrict__ bias,
    float* __restrict__ out, int n)
{
    extern __shared__ float sm[];
    float* As = sm;
    float* Ws = sm + 64 * K;
    int t = threadIdx.x;
    int row0 = blockIdx.x * 64;

    for (int i = t; i < 64 * K; i += 256) {
        int r = i / K, c = i % K;
        int gr = row0 + r;
        float v = 0.f;
        if (gr < n) {
            if (K == 64 || c < 64) v = A1[(size_t)gr * 64 + (c & 63)];
            else                   v = A2[(size_t)gr * 64 + (c - 64)];
        }
        As[i] = v;
    }
    for (int i = t; i < K * 64; i += 256) Ws[i] = W[i];
    __syncthreads();

    int tx = t & 15;
    int ty = t >> 4;
    float acc[4][4];
#pragma unroll
    for (int i = 0; i < 4; i++) { acc[i][0]=0.f; acc[i][1]=0.f; acc[i][2]=0.f; acc[i][3]=0.f; }

    const float4* Wq = (const float4*)Ws;
#pragma unroll 8
    for (int k = 0; k < K; k++) {
        float4 w = Wq[k * 16 + tx];
#pragma unroll
        for (int i = 0; i < 4; i++) {
            float av = As[(ty * 4 + i) * K + k];
            acc[i][0] += av * w.x; acc[i][1] += av * w.y;
            acc[i][2] += av * w.z; acc[i][3] += av * w.w;
        }
    }

    float b0 = bias[tx*4+0], b1 = bias[tx*4+1], b2 = bias[tx*4+2], b3 = bias[tx*4+3];
#pragma unroll
    for (int i = 0; i < 4; i++) {
        int row = row0 + ty * 4 + i;
        if (row < n) {
            float4 o;
            o.x = acc[i][0] + b0; o.y = acc[i][1] + b1;
            o.z = acc[i][2] + b2; o.w = acc[i][3] + b3;
            if (ACT) { o.x = silu_f(o.x); o.y = silu_f(o.y); o.z = silu_f(o.z); o.w = silu_f(o.w); }
            ((float4*)out)[(size_t)row * 16 + tx] = o;
        }
    }
}

__global__ void xupd_kernel(const float* __restrict__ x, const float* __restrict__ xacc,
                            float* __restrict__ out, int n3)
{
    int i = blockIdx.x * blockDim.x + threadIdx.x;
    if (i < n3) out[i] = x[i] + xacc[i];
}

// ------------------- launch -------------------
extern "C" void kernel_launch(void* const* d_in, const int* in_sizes, int n_in,
                              void* d_out, int out_size)
{
    const float* h0  = (const float*)d_in[0];
    const float* x0  = (const float*)d_in[1];
    const int*   src = (const int*)d_in[2];
    const int*   dst = (const int*)d_in[3];
    const float* ew1 = (const float*)d_in[4];
    const float* eb1 = (const float*)d_in[5];
    const float* ew2 = (const float*)d_in[6];
    const float* eb2 = (const float*)d_in[7];
    const float* nw1 = (const float*)d_in[8];
    const float* nb1 = (const float*)d_in[9];
    const float* nw2 = (const float*)d_in[10];
    const float* nb2 = (const float*)d_in[11];
    const float* cw1 = (const float*)d_in[12];
    const float* cb1 = (const float*)d_in[13];
    const float* cw2 = (const float*)d_in[14];

    int n = in_sizes[0] / 64;
    int E = in_sizes[2];

    float *P, *hA, *xA, *hacc, *xacc, *tb, *mbuf;
    int *deg, *off, *woff, *bsum, *bscan, *eidx;
    cudaGetSymbolAddress((void**)&P,    g_P);
    cudaGetSymbolAddress((void**)&hA,   g_hbuf);
    cudaGetSymbolAddress((void**)&xA,   g_xbuf);
    cudaGetSymbolAddress((void**)&hacc, g_hacc);
    cudaGetSymbolAddress((void**)&xacc, g_xacc);
    cudaGetSymbolAddress((void**)&tb,   g_t);
    cudaGetSymbolAddress((void**)&mbuf, g_m);
    cudaGetSymbolAddress((void**)&deg,  g_deg);
    cudaGetSymbolAddress((void**)&off,  g_off);
    cudaGetSymbolAddress((void**)&woff, g_woff);
    cudaGetSymbolAddress((void**)&bsum, g_bsum);
    cudaGetSymbolAddress((void**)&bscan,g_bscan);
    cudaGetSymbolAddress((void**)&eidx, g_eidx);

    float* hb[2] = { hA, hA + (size_t)NN * 64 };
    float* xb[2] = { xA, xA + (size_t)NN * 3 };

    const int smP  = (64*64 + 64*128) * 4;
    const int smE  = 13760 * 4;   // 55040 B
    const int smN1 = (64*128 + 128*64) * 4;
    const int smN2 = (64*64 + 64*64) * 4;
    cudaFuncSetAttribute(gemm_P_kernel, cudaFuncAttributeMaxDynamicSharedMemorySize, smP);
    cudaFuncSetAttribute(edge_kernel<true>,  cudaFuncAttributeMaxDynamicSharedMemorySize, smE);
    cudaFuncSetAttribute(edge_kernel<false>, cudaFuncAttributeMaxDynamicSharedMemorySize, smE);
    cudaFuncSetAttribute(node_gemm_kernel<128, true>,  cudaFuncAttributeMaxDynamicSharedMemorySize, smN1);
    cudaFuncSetAttribute(node_gemm_kernel<64, false>,  cudaFuncAttributeMaxDynamicSharedMemorySize, smN2);

    int nb_rows = (n + 63) / 64;
    int eb_blocks = (E + 127) / 128;
    int scan_nb = (n + 511) / 512;

    deg_zero_kernel<<<(n * 3 + 255) / 256, 256>>>(deg, xacc, n);
    deg_count_kernel<<<(E + 255) / 256, 256>>>(dst, deg, E);
    scan_blocks_kernel<<<scan_nb, 512>>>(deg, off, bsum, n);
    scan_bsums_kernel<<<1, 32>>>(bsum, bscan, scan_nb);
    scan_add_kernel<<<(n + 255) / 256, 256>>>(off, bscan, woff, n, E);
    fill_eidx_kernel<<<(E + 255) / 256, 256>>>(dst, woff, eidx, E);

    for (int d = 0; d < DEPTH; d++) {
        const float* hc = d ? hb[(d - 1) & 1] : h0;
        const float* xc = d ? xb[(d - 1) & 1] : x0;
        float* xo = (d == DEPTH - 1) ? (float*)d_out : xb[d & 1];

        if (d) zerox_kernel<<<(n * 3 + 255) / 256, 256>>>(xacc, n * 3);

        gemm_P_kernel<<<nb_rows, 256, smP>>>(hc, ew1 + (size_t)d * 129 * 64, P, n);

        if (d < DEPTH - 1) {
            edge_kernel<true><<<eb_blocks, 256, smE>>>(
                src, dst, xc, P,
                ew1 + (size_t)d * 129 * 64 + 128 * 64, eb1 + d * 64,
                ew2 + (size_t)d * 4096, eb2 + d * 64,
                cw1 + (size_t)d * 4096, cb1 + d * 64, cw2 + d * 64,
                mbuf, xacc, E);

            gather_kernel<<<(n * 32 + 255) / 256, 256>>>(mbuf, off, eidx, hacc, n);

            node_gemm_kernel<128, true><<<nb_rows, 256, smN1>>>(
                hc, hacc, nw1 + (size_t)d * 128 * 64, nb1 + d * 64, tb, n);
            node_gemm_kernel<64, false><<<nb_rows, 256, smN2>>>(
                tb, tb, nw2 + (size_t)d * 4096, nb2 + d * 64, hb[d & 1], n);
        } else {
            edge_kernel<false><<<eb_blocks, 256, smE>>>(
                src, dst, xc, P,
                ew1 + (size_t)d * 129 * 64 + 128 * 64, eb1 + d * 64,
                ew2 + (size_t)d * 4096, eb2 + d * 64,
                cw1 + (size_t)d * 4096, cb1 + d * 64, cw2 + d * 64,
                mbuf, xacc, E);
        }

        xupd_kernel<<<(n * 3 + 255) / 256, 256>>>(xc, xacc, xo, n * 3);
    }
}

// round 5
// speedup vs baseline: 1.6618x; 1.6167x over previous
#include <cuda_runtime.h>
#include <cuda_fp16.h>
#include <math.h>

#define NN 100000
#define EE 1600000
#define DEPTH 4

typedef unsigned int u32;

// ------------------- scratch (device globals; no runtime allocs) -------------------
__device__ float g_P[(size_t)NN * 128];
__device__ float g_hbuf[2][(size_t)NN * 64];
__device__ float g_xbuf[2][(size_t)NN * 3];
__device__ float g_hacc[(size_t)NN * 64];
__device__ float g_xacc[(size_t)NN * 3];
__device__ float g_t[(size_t)NN * 64];
__device__ float g_m[(size_t)EE * 64];
__device__ int   g_deg[NN];
__device__ int   g_off[NN + 1];
__device__ int   g_woff[NN];
__device__ int   g_bsum[256];
__device__ int   g_bscan[256];
__device__ int   g_eidx[EE];
__device__ __half g_wh[DEPTH * 2 * 4096];   // [d][0=ew2,1=cw1][4096] hi halves
__device__ __half g_wl[DEPTH * 2 * 4096];   // lo halves

// ------------------- helpers -------------------
__device__ __forceinline__ float silu_f(float v) {
    return __fdividef(v, 1.0f + __expf(-v));
}
__device__ __forceinline__ void red1(float* p, float a) {
    asm volatile("red.global.add.f32 [%0], %1;" :: "l"(p), "f"(a) : "memory");
}
__device__ __forceinline__ u32 smaddr(const void* p) {
    return (u32)__cvta_generic_to_shared(p);
}
__device__ __forceinline__ void ldsm4(u32* r, const void* p) {
    u32 a = smaddr(p);
    asm volatile("ldmatrix.sync.aligned.m8n8.x4.shared.b16 {%0,%1,%2,%3}, [%4];"
                 : "=r"(r[0]), "=r"(r[1]), "=r"(r[2]), "=r"(r[3]) : "r"(a));
}
__device__ __forceinline__ void ldsm2t(u32& b0, u32& b1, const void* p) {
    u32 a = smaddr(p);
    asm volatile("ldmatrix.sync.aligned.m8n8.x2.trans.shared.b16 {%0,%1}, [%2];"
                 : "=r"(b0), "=r"(b1) : "r"(a));
}
__device__ __forceinline__ void mma16816(float* c, const u32* a, u32 b0, u32 b1) {
    asm volatile("mma.sync.aligned.m16n8k16.row.col.f32.f16.f16.f32 "
                 "{%0,%1,%2,%3}, {%4,%5,%6,%7}, {%8,%9}, {%0,%1,%2,%3};"
                 : "+f"(c[0]), "+f"(c[1]), "+f"(c[2]), "+f"(c[3])
                 : "r"(a[0]), "r"(a[1]), "r"(a[2]), "r"(a[3]), "r"(b0), "r"(b1));
}
__device__ __forceinline__ void split1(float v, __half& h, __half& l) {
    h = __float2half_rn(v);
    l = __float2half_rn(v - __half2float(h));
}

// ------------------- weight pre-split -------------------
__global__ void wsplit_kernel(const float* __restrict__ ew2, const float* __restrict__ cw1,
                              __half* __restrict__ wh, __half* __restrict__ wl) {
    int i = blockIdx.x * blockDim.x + threadIdx.x;   // over DEPTH*2*4096
    if (i >= DEPTH * 2 * 4096) return;
    int d = i >> 13, which = (i >> 12) & 1, k = i & 4095;
    float v = which ? cw1[d * 4096 + k] : ew2[d * 4096 + k];
    __half h, l; split1(v, h, l);
    wh[i] = h; wl[i] = l;
}

// ------------------- CSR build -------------------
__global__ void deg_zero_kernel(int* __restrict__ deg, float* __restrict__ xacc, int n) {
    int i = blockIdx.x * blockDim.x + threadIdx.x;
    if (i < n) deg[i] = 0;
    if (i < n * 3) xacc[i] = 0.f;
}
__global__ void deg_count_kernel(const int* __restrict__ dst, int* __restrict__ deg, int E) {
    int e = blockIdx.x * blockDim.x + threadIdx.x;
    if (e < E) atomicAdd(&deg[dst[e]], 1);
}
__global__ void scan_blocks_kernel(const int* __restrict__ deg, int* __restrict__ off,
                                   int* __restrict__ bsum, int n) {
    __shared__ int s[512];
    int tid = threadIdx.x;
    int i = blockIdx.x * 512 + tid;
    int v = (i < n) ? deg[i] : 0;
    s[tid] = v;
    __syncthreads();
    for (int d = 1; d < 512; d <<= 1) {
        int t2 = (tid >= d) ? s[tid - d] : 0;
        __syncthreads();
        s[tid] += t2;
        __syncthreads();
    }
    if (i < n) off[i] = s[tid] - v;
    if (tid == 511) bsum[blockIdx.x] = s[511];
}
__global__ void scan_bsums_kernel(const int* __restrict__ bsum, int* __restrict__ bscan, int nb) {
    if (threadIdx.x == 0 && blockIdx.x == 0) {
        int acc = 0;
        for (int b = 0; b < nb; b++) { bscan[b] = acc; acc += bsum[b]; }
    }
}
__global__ void scan_add_kernel(int* __restrict__ off, const int* __restrict__ bscan,
                                int* __restrict__ woff, int n, int Etot) {
    int i = blockIdx.x * blockDim.x + threadIdx.x;
    if (i < n) {
        int v = off[i] + bscan[i >> 9];
        off[i] = v;
        woff[i] = v;
    }
    if (i == 0) off[n] = Etot;
}
__global__ void fill_eidx_kernel(const int* __restrict__ dst, int* __restrict__ woff,
                                 int* __restrict__ eidx, int E) {
    int e = blockIdx.x * blockDim.x + threadIdx.x;
    if (e < E) {
        int p = atomicAdd(&woff[dst[e]], 1);
        eidx[p] = e;
    }
}
__global__ void zerox_kernel(float* __restrict__ xacc, int n3) {
    int i = blockIdx.x * blockDim.x + threadIdx.x;
    if (i < n3) xacc[i] = 0.f;
}

// ------------------- P = h @ [Wa | Wb] -------------------
__global__ __launch_bounds__(256) void gemm_P_kernel(
    const float* __restrict__ h, const float* __restrict__ ew1,
    float* __restrict__ P, int n)
{
    extern __shared__ float sm[];
    float* As = sm;              // 64 x 64
    float* Ws = sm + 64 * 64;    // 64 x 128
    int t = threadIdx.x;
    int row0 = blockIdx.x * 64;

    for (int i = t; i < 64 * 64; i += 256) {
        int r = i >> 6, c = i & 63;
        int gr = row0 + r;
        As[i] = (gr < n) ? h[(size_t)gr * 64 + c] : 0.f;
    }
    for (int i = t; i < 64 * 128; i += 256) {
        int k = i >> 7, j = i & 127;
        Ws[i] = (j < 64) ? ew1[k * 64 + j] : ew1[(64 + k) * 64 + (j - 64)];
    }
    __syncthreads();

    int tx = t & 31;
    int ty = t >> 5;
    float acc[8][4];
#pragma unroll
    for (int i = 0; i < 8; i++) { acc[i][0]=0.f; acc[i][1]=0.f; acc[i][2]=0.f; acc[i][3]=0.f; }

    const float4* Wq = (const float4*)Ws;
#pragma unroll 8
    for (int k = 0; k < 64; k++) {
        float4 w = Wq[k * 32 + tx];
#pragma unroll
        for (int i = 0; i < 8; i++) {
            float av = As[(ty * 8 + i) * 64 + k];
            acc[i][0] += av * w.x; acc[i][1] += av * w.y;
            acc[i][2] += av * w.z; acc[i][3] += av * w.w;
        }
    }
#pragma unroll
    for (int i = 0; i < 8; i++) {
        int row = row0 + ty * 8 + i;
        if (row < n) {
            float4 o = make_float4(acc[i][0], acc[i][1], acc[i][2], acc[i][3]);
            ((float4*)P)[(size_t)row * 32 + tx] = o;
        }
    }
}

// ------------------- edge kernel: tensor-core (mma.sync fp16 split) -------------------
// smem halves layout:
//  sWh [64][72], sWl [64][72]        (current weight, split)
//  sA1h/sA1l [128][72]               (m1 split)
//  sA2h/sA2l [128][72]               (m split)
// then fp32: wr,eb1,eb2,cb1,cw2 (64 ea) | u0,u1,u2,cpart (128 ea) | di (128 int)
#define HW  (64 * 72)
#define HA  (128 * 72)
template<bool STORE>
__global__ __launch_bounds__(256, 2) void edge_kernel(
    const int* __restrict__ src, const int* __restrict__ dst,
    const float* __restrict__ x, const float* __restrict__ P,
    const float* __restrict__ wr,  const float* __restrict__ eb1,
    const __half* __restrict__ w1h, const __half* __restrict__ w1l,   // ew2 split
    const float* __restrict__ eb2,
    const __half* __restrict__ w2h, const __half* __restrict__ w2l,   // cw1 split
    const float* __restrict__ cb1, const float* __restrict__ cw2,
    float* __restrict__ mbuf, float* __restrict__ xacc, int E)
{
    extern __shared__ __half S[];
    __half* sWh  = S;
    __half* sWl  = S + HW;
    __half* sA1h = S + 2 * HW;
    __half* sA1l = S + 2 * HW + HA;
    __half* sA2h = S + 2 * HW + 2 * HA;
    __half* sA2l = S + 2 * HW + 3 * HA;
    float*  F    = (float*)(S + 2 * HW + 4 * HA);
    float* s_wr  = F;
    float* s_eb1 = F + 64;
    float* s_eb2 = F + 128;
    float* s_cb1 = F + 192;
    float* s_cw2 = F + 256;
    float* s_u0  = F + 320;
    float* s_u1  = F + 448;
    float* s_u2  = F + 576;
    float* s_cp  = F + 704;
    int*   s_di  = (int*)(F + 832);

    int t = threadIdx.x;
    int lane = t & 31, w = t >> 5;
    int em0 = blockIdx.x * 128;

    // ---- load small arrays + W1 (ew2 split) ----
    if (t < 64) {
        s_wr[t] = wr[t]; s_eb1[t] = eb1[t]; s_eb2[t] = eb2[t];
        s_cb1[t] = cb1[t]; s_cw2[t] = cw2[t];
    }
    {
        u32* dh = (u32*)sWh; u32* dl = (u32*)sWl;
        const u32* srh = (const u32*)w1h; const u32* srl = (const u32*)w1l;
#pragma unroll
        for (int i = t; i < 2048; i += 256) {
            int row = i >> 5, c2 = i & 31;
            dh[row * 36 + c2] = srh[row * 32 + c2];
            dl[row * 36 + c2] = srl[row * 32 + c2];
        }
    }
    __syncthreads();

    // ---- phase A: m1 = silu(P[src][0:64] + P[dst][64:128] + r*wr + eb1) -> sA1 ----
    {
        int eloc = t >> 1, ht = t & 1;
        int e = em0 + eloc;
        int si = 0, di = 0;
        float r = 0.f, u0 = 0.f, u1 = 0.f, u2 = 0.f;
        if (e < E) {
            si = src[e]; di = dst[e];
            float dx0 = x[si * 3 + 0] - x[di * 3 + 0];
            float dx1 = x[si * 3 + 1] - x[di * 3 + 1];
            float dx2 = x[si * 3 + 2] - x[di * 3 + 2];
            r = dx0 * dx0 + dx1 * dx1 + dx2 * dx2;
            float inv = __fdividef(1.0f, sqrtf(r) + 1e-30f);
            u0 = dx0 * inv; u1 = dx1 * inv; u2 = dx2 * inv;
        }
        if (ht == 0) {
            s_di[eloc] = di;
            s_u0[eloc] = u0; s_u1[eloc] = u1; s_u2[eloc] = u2;
        }
        const float4* Pa = (const float4*)(P + (size_t)si * 128) + ht * 8;
        const float4* Pb = (const float4*)(P + (size_t)di * 128 + 64) + ht * 8;
        __half* rh = sA1h + eloc * 72 + ht * 32;
        __half* rl = sA1l + eloc * 72 + ht * 32;
#pragma unroll
        for (int i = 0; i < 8; i++) {
            float4 va = Pa[i], vb = Pb[i];
            int f = ht * 32 + 4 * i;
            float v0 = silu_f(va.x + vb.x + r * s_wr[f+0] + s_eb1[f+0]);
            float v1 = silu_f(va.y + vb.y + r * s_wr[f+1] + s_eb1[f+1]);
            float v2 = silu_f(va.z + vb.z + r * s_wr[f+2] + s_eb1[f+2]);
            float v3 = silu_f(va.w + vb.w + r * s_wr[f+3] + s_eb1[f+3]);
            __half h0,h1,h2,h3,l0,l1,l2,l3;
            split1(v0,h0,l0); split1(v1,h1,l1); split1(v2,h2,l2); split1(v3,h3,l3);
            *(__half2*)(rh + 4*i)     = __halves2half2(h0, h1);
            *(__half2*)(rh + 4*i + 2) = __halves2half2(h2, h3);
            *(__half2*)(rl + 4*i)     = __halves2half2(l0, l1);
            *(__half2*)(rl + 4*i + 2) = __halves2half2(l2, l3);
        }
    }
    __syncthreads();

    // ---- GEMM1: m = silu(m1 @ ew2 + eb2) ----
    u32 Ah[16], Al[16];
#pragma unroll
    for (int ks = 0; ks < 4; ks++) {
        const __half* pa = sA1h + (16 * w + (lane & 15)) * 72 + 16 * ks + 8 * (lane >> 4);
        const __half* pl = sA1l + (16 * w + (lane & 15)) * 72 + 16 * ks + 8 * (lane >> 4);
        ldsm4(&Ah[4 * ks], pa);
        ldsm4(&Al[4 * ks], pl);
    }
#pragma unroll
    for (int nt = 0; nt < 8; nt++) {
        float acc[4] = {0.f, 0.f, 0.f, 0.f};
#pragma unroll
        for (int ks = 0; ks < 4; ks++) {
            u32 bh0, bh1, bl0, bl1;
            const __half* pb = sWh + (16 * ks + (lane & 15)) * 72 + 8 * nt;
            const __half* pc = sWl + (16 * ks + (lane & 15)) * 72 + 8 * nt;
            ldsm2t(bh0, bh1, pb);
            ldsm2t(bl0, bl1, pc);
            mma16816(acc, &Ah[4 * ks], bh0, bh1);
            mma16816(acc, &Ah[4 * ks], bl0, bl1);
            mma16816(acc, &Al[4 * ks], bh0, bh1);
        }
        int row = 16 * w + (lane >> 2);
        int col = 8 * nt + 2 * (lane & 3);
        float m0 = silu_f(acc[0] + s_eb2[col]);
        float m1 = silu_f(acc[1] + s_eb2[col + 1]);
        float m2 = silu_f(acc[2] + s_eb2[col]);
        float m3 = silu_f(acc[3] + s_eb2[col + 1]);
        __half h0,h1,h2,h3,l0,l1,l2,l3;
        split1(m0,h0,l0); split1(m1,h1,l1); split1(m2,h2,l2); split1(m3,h3,l3);
        *(__half2*)(sA2h + row * 72 + col)       = __halves2half2(h0, h1);
        *(__half2*)(sA2l + row * 72 + col)       = __halves2half2(l0, l1);
        *(__half2*)(sA2h + (row + 8) * 72 + col) = __halves2half2(h2, h3);
        *(__half2*)(sA2l + (row + 8) * 72 + col) = __halves2half2(l2, l3);
        if (STORE) {
            int e0 = em0 + row, e1 = em0 + row + 8;
            if (e0 < E) { float2 o; o.x = m0; o.y = m1; *(float2*)(mbuf + (size_t)e0 * 64 + col) = o; }
            if (e1 < E) { float2 o; o.x = m2; o.y = m3; *(float2*)(mbuf + (size_t)e1 * 64 + col) = o; }
        }
    }
    __syncthreads();

    // ---- reload W <- cw1 split ----
    {
        u32* dh = (u32*)sWh; u32* dl = (u32*)sWl;
        const u32* srh = (const u32*)w2h; const u32* srl = (const u32*)w2l;
#pragma unroll
        for (int i = t; i < 2048; i += 256) {
            int row = i >> 5, c2 = i & 31;
            dh[row * 36 + c2] = srh[row * 32 + c2];
            dl[row * 36 + c2] = srl[row * 32 + c2];
        }
    }
    __syncthreads();

    // ---- GEMM2: c1 = silu(m @ cw1 + cb1); c = c1 . cw2 ----
#pragma unroll
    for (int ks = 0; ks < 4; ks++) {
        const __half* pa = sA2h + (16 * w + (lane & 15)) * 72 + 16 * ks + 8 * (lane >> 4);
        const __half* pl = sA2l + (16 * w + (lane & 15)) * 72 + 16 * ks + 8 * (lane >> 4);
        ldsm4(&Ah[4 * ks], pa);
        ldsm4(&Al[4 * ks], pl);
    }
    float rs0 = 0.f, rs1 = 0.f;
#pragma unroll
    for (int nt = 0; nt < 8; nt++) {
        float acc[4] = {0.f, 0.f, 0.f, 0.f};
#pragma unroll
        for (int ks = 0; ks < 4; ks++) {
            u32 bh0, bh1, bl0, bl1;
            const __half* pb = sWh + (16 * ks + (lane & 15)) * 72 + 8 * nt;
            const __half* pc = sWl + (16 * ks + (lane & 15)) * 72 + 8 * nt;
            ldsm2t(bh0, bh1, pb);
            ldsm2t(bl0, bl1, pc);
            mma16816(acc, &Ah[4 * ks], bh0, bh1);
            mma16816(acc, &Ah[4 * ks], bl0, bl1);
            mma16816(acc, &Al[4 * ks], bh0, bh1);
        }
        int col = 8 * nt + 2 * (lane & 3);
        rs0 += silu_f(acc[0] + s_cb1[col]) * s_cw2[col]
             + silu_f(acc[1] + s_cb1[col + 1]) * s_cw2[col + 1];
        rs1 += silu_f(acc[2] + s_cb1[col]) * s_cw2[col]
             + silu_f(acc[3] + s_cb1[col + 1]) * s_cw2[col + 1];
    }
    rs0 += __shfl_xor_sync(0xffffffffu, rs0, 1);
    rs0 += __shfl_xor_sync(0xffffffffu, rs0, 2);
    rs1 += __shfl_xor_sync(0xffffffffu, rs1, 1);
    rs1 += __shfl_xor_sync(0xffffffffu, rs1, 2);
    if ((lane & 3) == 0) {
        s_cp[16 * w + (lane >> 2)]     = rs0;
        s_cp[16 * w + 8 + (lane >> 2)] = rs1;
    }
    __syncthreads();

    if (t < 128) {
        int e = em0 + t;
        if (e < E) {
            float c = s_cp[t];
            int di = s_di[t];
            float* xp = xacc + (size_t)di * 3;
            red1(xp + 0, c * s_u0[t]);
            red1(xp + 1, c * s_u1[t]);
            red1(xp + 2, c * s_u2[t]);
        }
    }
}

// ------------------- gather -------------------
__global__ void gather_kernel(const float* __restrict__ m, const int* __restrict__ off,
                              const int* __restrict__ eidx, float* __restrict__ hn, int n)
{
    int warp = (blockIdx.x * blockDim.x + threadIdx.x) >> 5;
    int lane = threadIdx.x & 31;
    if (warp >= n) return;
    int b = off[warp], en = off[warp + 1];
    float ax = 0.f, ay = 0.f;
    for (int i = b; i < en; i++) {
        int eid = eidx[i];
        float2 v = ((const float2*)(m + (size_t)eid * 64))[lane];
        ax += v.x; ay += v.y;
    }
    float2 o; o.x = ax; o.y = ay;
    ((float2*)(hn + (size_t)warp * 64))[lane] = o;
}

// ------------------- node GEMM -------------------
template<int K, bool ACT>
__global__ __launch_bounds__(256) void node_gemm_kernel(
    const float* __restrict__ A1, const float* __restrict__ A2,
    const float* __restrict__ W, const float* __restrict__ bias,
    float* __restrict__ out, int n)
{
    extern __shared__ float sm[];
    float* As = sm;
    float* Ws = sm + 64 * K;
    int t = threadIdx.x;
    int row0 = blockIdx.x * 64;

    for (int i = t; i < 64 * K; i += 256) {
        int r = i / K, c = i % K;
        int gr = row0 + r;
        float v = 0.f;
        if (gr < n) {
            if (K == 64 || c < 64) v = A1[(size_t)gr * 64 + (c & 63)];
            else                   v = A2[(size_t)gr * 64 + (c - 64)];
        }
        As[i] = v;
    }
    for (int i = t; i < K * 64; i += 256) Ws[i] = W[i];
    __syncthreads();

    int tx = t & 15;
    int ty = t >> 4;
    float acc[4][4];
#pragma unroll
    for (int i = 0; i < 4; i++) { acc[i][0]=0.f; acc[i][1]=0.f; acc[i][2]=0.f; acc[i][3]=0.f; }

    const float4* Wq = (const float4*)Ws;
#pragma unroll 8
    for (int k = 0; k < K; k++) {
        float4 w = Wq[k * 16 + tx];
#pragma unroll
        for (int i = 0; i < 4; i++) {
            float av = As[(ty * 4 + i) * K + k];
            acc[i][0] += av * w.x; acc[i][1] += av * w.y;
            acc[i][2] += av * w.z; acc[i][3] += av * w.w;
        }
    }

    float b0 = bias[tx*4+0], b1 = bias[tx*4+1], b2 = bias[tx*4+2], b3 = bias[tx*4+3];
#pragma unroll
    for (int i = 0; i < 4; i++) {
        int row = row0 + ty * 4 + i;
        if (row < n) {
            float4 o;
            o.x = acc[i][0] + b0; o.y = acc[i][1] + b1;
            o.z = acc[i][2] + b2; o.w = acc[i][3] + b3;
            if (ACT) { o.x = silu_f(o.x); o.y = silu_f(o.y); o.z = silu_f(o.z); o.w = silu_f(o.w); }
            ((float4*)out)[(size_t)row * 16 + tx] = o;
        }
    }
}

__global__ void xupd_kernel(const float* __restrict__ x, const float* __restrict__ xacc,
                            float* __restrict__ out, int n3)
{
    int i = blockIdx.x * blockDim.x + threadIdx.x;
    if (i < n3) out[i] = x[i] + xacc[i];
}

// ------------------- launch -------------------
extern "C" void kernel_launch(void* const* d_in, const int* in_sizes, int n_in,
                              void* d_out, int out_size)
{
    const float* h0  = (const float*)d_in[0];
    const float* x0  = (const float*)d_in[1];
    const int*   src = (const int*)d_in[2];
    const int*   dst = (const int*)d_in[3];
    const float* ew1 = (const float*)d_in[4];
    const float* eb1 = (const float*)d_in[5];
    const float* ew2 = (const float*)d_in[6];
    const float* eb2 = (const float*)d_in[7];
    const float* nw1 = (const float*)d_in[8];
    const float* nb1 = (const float*)d_in[9];
    const float* nw2 = (const float*)d_in[10];
    const float* nb2 = (const float*)d_in[11];
    const float* cw1 = (const float*)d_in[12];
    const float* cb1 = (const float*)d_in[13];
    const float* cw2 = (const float*)d_in[14];

    int n = in_sizes[0] / 64;
    int E = in_sizes[2];

    float *P, *hA, *xA, *hacc, *xacc, *tb, *mbuf;
    int *deg, *off, *woff, *bsum, *bscan, *eidx;
    __half *wh, *wl;
    cudaGetSymbolAddress((void**)&P,    g_P);
    cudaGetSymbolAddress((void**)&hA,   g_hbuf);
    cudaGetSymbolAddress((void**)&xA,   g_xbuf);
    cudaGetSymbolAddress((void**)&hacc, g_hacc);
    cudaGetSymbolAddress((void**)&xacc, g_xacc);
    cudaGetSymbolAddress((void**)&tb,   g_t);
    cudaGetSymbolAddress((void**)&mbuf, g_m);
    cudaGetSymbolAddress((void**)&deg,  g_deg);
    cudaGetSymbolAddress((void**)&off,  g_off);
    cudaGetSymbolAddress((void**)&woff, g_woff);
    cudaGetSymbolAddress((void**)&bsum, g_bsum);
    cudaGetSymbolAddress((void**)&bscan,g_bscan);
    cudaGetSymbolAddress((void**)&eidx, g_eidx);
    cudaGetSymbolAddress((void**)&wh,   g_wh);
    cudaGetSymbolAddress((void**)&wl,   g_wl);

    float* hb[2] = { hA, hA + (size_t)NN * 64 };
    float* xb[2] = { xA, xA + (size_t)NN * 3 };

    const int smP  = (64*64 + 64*128) * 4;
    const int smE  = (2 * HW + 4 * HA) * 2 + 960 * 4;   // halves*2B + fp32 tail
    const int smN1 = (64*128 + 128*64) * 4;
    const int smN2 = (64*64 + 64*64) * 4;
    cudaFuncSetAttribute(gemm_P_kernel, cudaFuncAttributeMaxDynamicSharedMemorySize, smP);
    cudaFuncSetAttribute(edge_kernel<true>,  cudaFuncAttributeMaxDynamicSharedMemorySize, smE);
    cudaFuncSetAttribute(edge_kernel<false>, cudaFuncAttributeMaxDynamicSharedMemorySize, smE);
    cudaFuncSetAttribute(node_gemm_kernel<128, true>,  cudaFuncAttributeMaxDynamicSharedMemorySize, smN1);
    cudaFuncSetAttribute(node_gemm_kernel<64, false>,  cudaFuncAttributeMaxDynamicSharedMemorySize, smN2);

    int nb_rows = (n + 63) / 64;
    int eb_blocks = (E + 127) / 128;
    int scan_nb = (n + 511) / 512;

    // launch order puts edge_kernel(layer 0) at index 3 for ncu
    deg_zero_kernel<<<(n * 3 + 255) / 256, 256>>>(deg, xacc, n);                       // 0
    gemm_P_kernel<<<nb_rows, 256, smP>>>(h0, ew1, P, n);                               // 1
    wsplit_kernel<<<(DEPTH * 2 * 4096 + 255) / 256, 256>>>(ew2, cw1, wh, wl);          // 2

    for (int d = 0; d < DEPTH; d++) {
        const float* hc = d ? hb[(d - 1) & 1] : h0;
        const float* xc = d ? xb[(d - 1) & 1] : x0;
        float* xo = (d == DEPTH - 1) ? (float*)d_out : xb[d & 1];

        if (d) {
            zerox_kernel<<<(n * 3 + 255) / 256, 256>>>(xacc, n * 3);
            gemm_P_kernel<<<nb_rows, 256, smP>>>(hc, ew1 + (size_t)d * 129 * 64, P, n);
        }

        const __half* w1h = wh + (size_t)(2 * d) * 4096;
        const __half* w1l = wl + (size_t)(2 * d) * 4096;
        const __half* w2h = wh + (size_t)(2 * d + 1) * 4096;
        const __half* w2l = wl + (size_t)(2 * d + 1) * 4096;
        const float* wrp = ew1 + (size_t)d * 129 * 64 + 128 * 64;

        if (d < DEPTH - 1) {
            edge_kernel<true><<<eb_blocks, 256, smE>>>(
                src, dst, xc, P, wrp, eb1 + d * 64,
                w1h, w1l, eb2 + d * 64, w2h, w2l,
                cb1 + d * 64, cw2 + d * 64, mbuf, xacc, E);               // layer0: idx 3

            if (d == 0) {
                deg_count_kernel<<<(E + 255) / 256, 256>>>(dst, deg, E);
                scan_blocks_kernel<<<scan_nb, 512>>>(deg, off, bsum, n);
                scan_bsums_kernel<<<1, 32>>>(bsum, bscan, scan_nb);
                scan_add_kernel<<<(n + 255) / 256, 256>>>(off, bscan, woff, n, E);
                fill_eidx_kernel<<<(E + 255) / 256, 256>>>(dst, woff, eidx, E);
            }

            gather_kernel<<<(n * 32 + 255) / 256, 256>>>(mbuf, off, eidx, hacc, n);

            node_gemm_kernel<128, true><<<nb_rows, 256, smN1>>>(
                hc, hacc, nw1 + (size_t)d * 128 * 64, nb1 + d * 64, tb, n);
            node_gemm_kernel<64, false><<<nb_rows, 256, smN2>>>(
                tb, tb, nw2 + (size_t)d * 4096, nb2 + d * 64, hb[d & 1], n);
        } else {
            edge_kernel<false><<<eb_blocks, 256, smE>>>(
                src, dst, xc, P, wrp, eb1 + d * 64,
                w1h, w1l, eb2 + d * 64, w2h, w2l,
                cb1 + d * 64, cw2 + d * 64, mbuf, xacc, E);
        }

        xupd_kernel<<<(n * 3 + 255) / 256, 256>>>(xc, xacc, xo, n * 3);
    }
}

// round 6
// speedup vs baseline: 1.8742x; 1.1279x over previous
#include <cuda_runtime.h>
#include <cuda_fp16.h>
#include <math.h>

#define NN 100000
#define EE 1600000
#define DEPTH 4

typedef unsigned int u32;

// ------------------- scratch (device globals; no runtime allocs) -------------------
__device__ float g_P[(size_t)NN * 128];
__device__ float g_hbuf[2][(size_t)NN * 64];
__device__ float g_xbuf[2][(size_t)NN * 3];
__device__ float g_hacc[(size_t)NN * 64];
__device__ float g_xacc[(size_t)NN * 3];
__device__ float g_t[(size_t)NN * 64];
__device__ float g_m[(size_t)EE * 64];
__device__ int   g_deg[NN];
__device__ int   g_off[NN + 1];
__device__ int   g_woff[NN];
__device__ int   g_bsum[256];
__device__ int   g_bscan[256];
__device__ int   g_eidx[EE];
__device__ __half g_wh[DEPTH * 2 * 4096];   // [d][0=ew2,1=cw1][4096] hi halves
__device__ __half g_wl[DEPTH * 2 * 4096];   // lo halves

// ------------------- helpers -------------------
__device__ __forceinline__ float silu_f(float v) {
    return __fdividef(v, 1.0f + __expf(-v));
}
__device__ __forceinline__ void red1(float* p, float a) {
    asm volatile("red.global.add.f32 [%0], %1;" :: "l"(p), "f"(a) : "memory");
}
__device__ __forceinline__ u32 smaddr(const void* p) {
    return (u32)__cvta_generic_to_shared(p);
}
__device__ __forceinline__ void ldsm4(u32* r, const void* p) {
    u32 a = smaddr(p);
    asm volatile("ldmatrix.sync.aligned.m8n8.x4.shared.b16 {%0,%1,%2,%3}, [%4];"
                 : "=r"(r[0]), "=r"(r[1]), "=r"(r[2]), "=r"(r[3]) : "r"(a));
}
__device__ __forceinline__ void ldsm2t(u32& b0, u32& b1, const void* p) {
    u32 a = smaddr(p);
    asm volatile("ldmatrix.sync.aligned.m8n8.x2.trans.shared.b16 {%0,%1}, [%2];"
                 : "=r"(b0), "=r"(b1) : "r"(a));
}
__device__ __forceinline__ void mma16816(float* c, const u32* a, u32 b0, u32 b1) {
    asm volatile("mma.sync.aligned.m16n8k16.row.col.f32.f16.f16.f32 "
                 "{%0,%1,%2,%3}, {%4,%5,%6,%7}, {%8,%9}, {%0,%1,%2,%3};"
                 : "+f"(c[0]), "+f"(c[1]), "+f"(c[2]), "+f"(c[3])
                 : "r"(a[0]), "r"(a[1]), "r"(a[2]), "r"(a[3]), "r"(b0), "r"(b1));
}
__device__ __forceinline__ void split1(float v, __half& h, __half& l) {
    h = __float2half_rn(v);
    l = __float2half_rn(v - __half2float(h));
}
__device__ __forceinline__ u32 packh2(__half a, __half b) {
    __half2 h = __halves2half2(a, b);
    return *(u32*)&h;
}

// ------------------- weight pre-split -------------------
__global__ void wsplit_kernel(const float* __restrict__ ew2, const float* __restrict__ cw1,
                              __half* __restrict__ wh, __half* __restrict__ wl) {
    int i = blockIdx.x * blockDim.x + threadIdx.x;   // over DEPTH*2*4096
    if (i >= DEPTH * 2 * 4096) return;
    int d = i >> 13, which = (i >> 12) & 1, k = i & 4095;
    float v = which ? cw1[d * 4096 + k] : ew2[d * 4096 + k];
    __half h, l; split1(v, h, l);
    wh[i] = h; wl[i] = l;
}

// ------------------- CSR build -------------------
__global__ void deg_zero_kernel(int* __restrict__ deg, float* __restrict__ xacc, int n) {
    int i = blockIdx.x * blockDim.x + threadIdx.x;
    if (i < n) deg[i] = 0;
    if (i < n * 3) xacc[i] = 0.f;
}
__global__ void deg_count_kernel(const int* __restrict__ dst, int* __restrict__ deg, int E) {
    int e = blockIdx.x * blockDim.x + threadIdx.x;
    if (e < E) atomicAdd(&deg[dst[e]], 1);
}
__global__ void scan_blocks_kernel(const int* __restrict__ deg, int* __restrict__ off,
                                   int* __restrict__ bsum, int n) {
    __shared__ int s[512];
    int tid = threadIdx.x;
    int i = blockIdx.x * 512 + tid;
    int v = (i < n) ? deg[i] : 0;
    s[tid] = v;
    __syncthreads();
    for (int d = 1; d < 512; d <<= 1) {
        int t2 = (tid >= d) ? s[tid - d] : 0;
        __syncthreads();
        s[tid] += t2;
        __syncthreads();
    }
    if (i < n) off[i] = s[tid] - v;
    if (tid == 511) bsum[blockIdx.x] = s[511];
}
__global__ void scan_bsums_kernel(const int* __restrict__ bsum, int* __restrict__ bscan, int nb) {
    if (threadIdx.x == 0 && blockIdx.x == 0) {
        int acc = 0;
        for (int b = 0; b < nb; b++) { bscan[b] = acc; acc += bsum[b]; }
    }
}
__global__ void scan_add_kernel(int* __restrict__ off, const int* __restrict__ bscan,
                                int* __restrict__ woff, int n, int Etot) {
    int i = blockIdx.x * blockDim.x + threadIdx.x;
    if (i < n) {
        int v = off[i] + bscan[i >> 9];
        off[i] = v;
        woff[i] = v;
    }
    if (i == 0) off[n] = Etot;
}
__global__ void fill_eidx_kernel(const int* __restrict__ dst, int* __restrict__ woff,
                                 int* __restrict__ eidx, int E) {
    int e = blockIdx.x * blockDim.x + threadIdx.x;
    if (e < E) {
        int p = atomicAdd(&woff[dst[e]], 1);
        eidx[p] = e;
    }
}
__global__ void zerox_kernel(float* __restrict__ xacc, int n3) {
    int i = blockIdx.x * blockDim.x + threadIdx.x;
    if (i < n3) xacc[i] = 0.f;
}

// ------------------- P = h @ [Wa | Wb] -------------------
__global__ __launch_bounds__(256) void gemm_P_kernel(
    const float* __restrict__ h, const float* __restrict__ ew1,
    float* __restrict__ P, int n)
{
    extern __shared__ float sm[];
    float* As = sm;              // 64 x 64
    float* Ws = sm + 64 * 64;    // 64 x 128
    int t = threadIdx.x;
    int row0 = blockIdx.x * 64;

    for (int i = t; i < 64 * 64; i += 256) {
        int r = i >> 6, c = i & 63;
        int gr = row0 + r;
        As[i] = (gr < n) ? h[(size_t)gr * 64 + c] : 0.f;
    }
    for (int i = t; i < 64 * 128; i += 256) {
        int k = i >> 7, j = i & 127;
        Ws[i] = (j < 64) ? ew1[k * 64 + j] : ew1[(64 + k) * 64 + (j - 64)];
    }
    __syncthreads();

    int tx = t & 31;
    int ty = t >> 5;
    float acc[8][4];
#pragma unroll
    for (int i = 0; i < 8; i++) { acc[i][0]=0.f; acc[i][1]=0.f; acc[i][2]=0.f; acc[i][3]=0.f; }

    const float4* Wq = (const float4*)Ws;
#pragma unroll 8
    for (int k = 0; k < 64; k++) {
        float4 w = Wq[k * 32 + tx];
#pragma unroll
        for (int i = 0; i < 8; i++) {
            float av = As[(ty * 8 + i) * 64 + k];
            acc[i][0] += av * w.x; acc[i][1] += av * w.y;
            acc[i][2] += av * w.z; acc[i][3] += av * w.w;
        }
    }
#pragma unroll
    for (int i = 0; i < 8; i++) {
        int row = row0 + ty * 8 + i;
        if (row < n) {
            float4 o = make_float4(acc[i][0], acc[i][1], acc[i][2], acc[i][3]);
            ((float4*)P)[(size_t)row * 32 + tx] = o;
        }
    }
}

// ------------------- edge kernel: tensor-core, register fragment reuse -------------------
// smem halves: sW1h/sW1l/sW2h/sW2l [64][72] each | sA1h/sA1l [128][72]
// fp32 tail: wr,eb1,eb2,cb1,cw2 (64 ea) | u0,u1,u2,cp (128 ea) | di (128 int)
#define HW  (64 * 72)
#define HA  (128 * 72)
template<bool STORE>
__global__ __launch_bounds__(256, 2) void edge_kernel(
    const int* __restrict__ src, const int* __restrict__ dst,
    const float* __restrict__ x, const float* __restrict__ P,
    const float* __restrict__ wr,  const float* __restrict__ eb1,
    const __half* __restrict__ w1h, const __half* __restrict__ w1l,   // ew2 split
    const float* __restrict__ eb2,
    const __half* __restrict__ w2h, const __half* __restrict__ w2l,   // cw1 split
    const float* __restrict__ cb1, const float* __restrict__ cw2,
    float* __restrict__ mbuf, float* __restrict__ xacc, int E)
{
    extern __shared__ __half S[];
    __half* sW1h = S;
    __half* sW1l = S + HW;
    __half* sW2h = S + 2 * HW;
    __half* sW2l = S + 3 * HW;
    __half* sA1h = S + 4 * HW;
    __half* sA1l = S + 4 * HW + HA;
    float*  F    = (float*)(S + 4 * HW + 2 * HA);
    float* s_wr  = F;
    float* s_eb1 = F + 64;
    float* s_eb2 = F + 128;
    float* s_cb1 = F + 192;
    float* s_cw2 = F + 256;
    float* s_u0  = F + 320;
    float* s_u1  = F + 448;
    float* s_u2  = F + 576;
    float* s_cp  = F + 704;
    int*   s_di  = (int*)(F + 832);

    int t = threadIdx.x;
    int lane = t & 31, w = t >> 5;
    int em0 = blockIdx.x * 128;

    // ---- load small arrays + BOTH weight splits (once) ----
    if (t < 64) {
        s_wr[t] = wr[t]; s_eb1[t] = eb1[t]; s_eb2[t] = eb2[t];
        s_cb1[t] = cb1[t]; s_cw2[t] = cw2[t];
    }
    {
        u32* d1h = (u32*)sW1h; u32* d1l = (u32*)sW1l;
        u32* d2h = (u32*)sW2h; u32* d2l = (u32*)sW2l;
        const u32* s1h = (const u32*)w1h; const u32* s1l = (const u32*)w1l;
        const u32* s2h = (const u32*)w2h; const u32* s2l = (const u32*)w2l;
#pragma unroll
        for (int i = t; i < 2048; i += 256) {
            int row = i >> 5, c2 = i & 31;
            d1h[row * 36 + c2] = s1h[row * 32 + c2];
            d1l[row * 36 + c2] = s1l[row * 32 + c2];
            d2h[row * 36 + c2] = s2h[row * 32 + c2];
            d2l[row * 36 + c2] = s2l[row * 32 + c2];
        }
    }
    __syncthreads();

    // ---- phase A: m1 = silu(P[src][0:64] + P[dst][64:128] + r*wr + eb1) -> sA1 ----
    {
        int eloc = t >> 1, ht = t & 1;
        int e = em0 + eloc;
        int si = 0, di = 0;
        float r = 0.f, u0 = 0.f, u1 = 0.f, u2 = 0.f;
        if (e < E) {
            si = src[e]; di = dst[e];
            float dx0 = x[si * 3 + 0] - x[di * 3 + 0];
            float dx1 = x[si * 3 + 1] - x[di * 3 + 1];
            float dx2 = x[si * 3 + 2] - x[di * 3 + 2];
            r = dx0 * dx0 + dx1 * dx1 + dx2 * dx2;
            float inv = __fdividef(1.0f, sqrtf(r) + 1e-30f);
            u0 = dx0 * inv; u1 = dx1 * inv; u2 = dx2 * inv;
        }
        if (ht == 0) {
            s_di[eloc] = di;
            s_u0[eloc] = u0; s_u1[eloc] = u1; s_u2[eloc] = u2;
        }
        const float4* Pa = (const float4*)(P + (size_t)si * 128) + ht * 8;
        const float4* Pb = (const float4*)(P + (size_t)di * 128 + 64) + ht * 8;
        __half* rh = sA1h + eloc * 72 + ht * 32;
        __half* rl = sA1l + eloc * 72 + ht * 32;
#pragma unroll
        for (int i = 0; i < 8; i++) {
            float4 va = Pa[i], vb = Pb[i];
            int f = ht * 32 + 4 * i;
            float v0 = silu_f(va.x + vb.x + r * s_wr[f+0] + s_eb1[f+0]);
            float v1 = silu_f(va.y + vb.y + r * s_wr[f+1] + s_eb1[f+1]);
            float v2 = silu_f(va.z + vb.z + r * s_wr[f+2] + s_eb1[f+2]);
            float v3 = silu_f(va.w + vb.w + r * s_wr[f+3] + s_eb1[f+3]);
            __half h0,h1,h2,h3,l0,l1,l2,l3;
            split1(v0,h0,l0); split1(v1,h1,l1); split1(v2,h2,l2); split1(v3,h3,l3);
            *(__half2*)(rh + 4*i)     = __halves2half2(h0, h1);
            *(__half2*)(rh + 4*i + 2) = __halves2half2(h2, h3);
            *(__half2*)(rl + 4*i)     = __halves2half2(l0, l1);
            *(__half2*)(rl + 4*i + 2) = __halves2half2(l2, l3);
        }
    }
    __syncthreads();

    // ---- GEMM1: m = silu(m1 @ ew2 + eb2), accumulate full 64-col row strip ----
    u32 Ah[16], Al[16];
#pragma unroll
    for (int ks = 0; ks < 4; ks++) {
        const __half* pa = sA1h + (16 * w + (lane & 15)) * 72 + 16 * ks + 8 * (lane >> 4);
        const __half* pl = sA1l + (16 * w + (lane & 15)) * 72 + 16 * ks + 8 * (lane >> 4);
        ldsm4(&Ah[4 * ks], pa);
        ldsm4(&Al[4 * ks], pl);
    }
    float accs[8][4];
#pragma unroll
    for (int nt = 0; nt < 8; nt++) {
        float* acc = accs[nt];
        acc[0] = 0.f; acc[1] = 0.f; acc[2] = 0.f; acc[3] = 0.f;
#pragma unroll
        for (int ks = 0; ks < 4; ks++) {
            u32 bh0, bh1, bl0, bl1;
            ldsm2t(bh0, bh1, sW1h + (16 * ks + (lane & 15)) * 72 + 8 * nt);
            ldsm2t(bl0, bl1, sW1l + (16 * ks + (lane & 15)) * 72 + 8 * nt);
            mma16816(acc, &Ah[4 * ks], bh0, bh1);
            mma16816(acc, &Ah[4 * ks], bl0, bl1);
            mma16816(acc, &Al[4 * ks], bh0, bh1);
        }
    }

    // ---- epilogue: silu, store m, split into GEMM2 A fragments IN REGISTERS ----
    // C frag (nt) -> A frag (ks=nt>>1, pos=nt&1): a[4ks+2pos+0]=pack(c0,c1), a[4ks+2pos+1]=pack(c2,c3)
    u32 A2h[16], A2l[16];
    int row = 16 * w + (lane >> 2);
#pragma unroll
    for (int nt = 0; nt < 8; nt++) {
        int col = 8 * nt + 2 * (lane & 3);
        float m0 = silu_f(accs[nt][0] + s_eb2[col]);
        float m1 = silu_f(accs[nt][1] + s_eb2[col + 1]);
        float m2 = silu_f(accs[nt][2] + s_eb2[col]);
        float m3 = silu_f(accs[nt][3] + s_eb2[col + 1]);
        if (STORE) {
            int e0 = em0 + row, e1 = em0 + row + 8;
            if (e0 < E) { float2 o; o.x = m0; o.y = m1; *(float2*)(mbuf + (size_t)e0 * 64 + col) = o; }
            if (e1 < E) { float2 o; o.x = m2; o.y = m3; *(float2*)(mbuf + (size_t)e1 * 64 + col) = o; }
        }
        __half h0,h1,h2,h3,l0,l1,l2,l3;
        split1(m0,h0,l0); split1(m1,h1,l1); split1(m2,h2,l2); split1(m3,h3,l3);
        int base = 4 * (nt >> 1) + 2 * (nt & 1);
        A2h[base + 0] = packh2(h0, h1);
        A2h[base + 1] = packh2(h2, h3);
        A2l[base + 0] = packh2(l0, l1);
        A2l[base + 1] = packh2(l2, l3);
    }

    // ---- GEMM2: c1 = silu(m @ cw1 + cb1); c = c1 . cw2 (no smem round-trip) ----
    float rs0 = 0.f, rs1 = 0.f;
#pragma unroll
    for (int nt = 0; nt < 8; nt++) {
        float acc[4] = {0.f, 0.f, 0.f, 0.f};
#pragma unroll
        for (int ks = 0; ks < 4; ks++) {
            u32 bh0, bh1, bl0, bl1;
            ldsm2t(bh0, bh1, sW2h + (16 * ks + (lane & 15)) * 72 + 8 * nt);
            ldsm2t(bl0, bl1, sW2l + (16 * ks + (lane & 15)) * 72 + 8 * nt);
            mma16816(acc, &A2h[4 * ks], bh0, bh1);
            mma16816(acc, &A2h[4 * ks], bl0, bl1);
            mma16816(acc, &A2l[4 * ks], bh0, bh1);
        }
        int col = 8 * nt + 2 * (lane & 3);
        rs0 += silu_f(acc[0] + s_cb1[col]) * s_cw2[col]
             + silu_f(acc[1] + s_cb1[col + 1]) * s_cw2[col + 1];
        rs1 += silu_f(acc[2] + s_cb1[col]) * s_cw2[col]
             + silu_f(acc[3] + s_cb1[col + 1]) * s_cw2[col + 1];
    }
    rs0 += __shfl_xor_sync(0xffffffffu, rs0, 1);
    rs0 += __shfl_xor_sync(0xffffffffu, rs0, 2);
    rs1 += __shfl_xor_sync(0xffffffffu, rs1, 1);
    rs1 += __shfl_xor_sync(0xffffffffu, rs1, 2);
    if ((lane & 3) == 0) {
        s_cp[16 * w + (lane >> 2)]     = rs0;
        s_cp[16 * w + 8 + (lane >> 2)] = rs1;
    }
    __syncthreads();

    if (t < 128) {
        int e = em0 + t;
        if (e < E) {
            float c = s_cp[t];
            int di = s_di[t];
            float* xp = xacc + (size_t)di * 3;
            red1(xp + 0, c * s_u0[t]);
            red1(xp + 1, c * s_u1[t]);
            red1(xp + 2, c * s_u2[t]);
        }
    }
}

// ------------------- gather -------------------
__global__ void gather_kernel(const float* __restrict__ m, const int* __restrict__ off,
                              const int* __restrict__ eidx, float* __restrict__ hn, int n)
{
    int warp = (blockIdx.x * blockDim.x + threadIdx.x) >> 5;
    int lane = threadIdx.x & 31;
    if (warp >= n) return;
    int b = off[warp], en = off[warp + 1];
    float ax = 0.f, ay = 0.f;
    for (int i = b; i < en; i++) {
        int eid = eidx[i];
        float2 v = ((const float2*)(m + (size_t)eid * 64))[lane];
        ax += v.x; ay += v.y;
    }
    float2 o; o.x = ax; o.y = ay;
    ((float2*)(hn + (size_t)warp * 64))[lane] = o;
}

// ------------------- node GEMM -------------------
template<int K, bool ACT>
__global__ __launch_bounds__(256) void node_gemm_kernel(
    const float* __restrict__ A1, const float* __restrict__ A2,
    const float* __restrict__ W, const float* __restrict__ bias,
    float* __restrict__ out, int n)
{
    extern __shared__ float sm[];
    float* As = sm;
    float* Ws = sm + 64 * K;
    int t = threadIdx.x;
    int row0 = blockIdx.x * 64;

    for (int i = t; i < 64 * K; i += 256) {
        int r = i / K, c = i % K;
        int gr = row0 + r;
        float v = 0.f;
        if (gr < n) {
            if (K == 64 || c < 64) v = A1[(size_t)gr * 64 + (c & 63)];
            else                   v = A2[(size_t)gr * 64 + (c - 64)];
        }
        As[i] = v;
    }
    for (int i = t; i < K * 64; i += 256) Ws[i] = W[i];
    __syncthreads();

    int tx = t & 15;
    int ty = t >> 4;
    float acc[4][4];
#pragma unroll
    for (int i = 0; i < 4; i++) { acc[i][0]=0.f; acc[i][1]=0.f; acc[i][2]=0.f; acc[i][3]=0.f; }

    const float4* Wq = (const float4*)Ws;
#pragma unroll 8
    for (int k = 0; k < K; k++) {
        float4 w = Wq[k * 16 + tx];
#pragma unroll
        for (int i = 0; i < 4; i++) {
            float av = As[(ty * 4 + i) * K + k];
            acc[i][0] += av * w.x; acc[i][1] += av * w.y;
            acc[i][2] += av * w.z; acc[i][3] += av * w.w;
        }
    }

    float b0 = bias[tx*4+0], b1 = bias[tx*4+1], b2 = bias[tx*4+2], b3 = bias[tx*4+3];
#pragma unroll
    for (int i = 0; i < 4; i++) {
        int row = row0 + ty * 4 + i;
        if (row < n) {
            float4 o;
            o.x = acc[i][0] + b0; o.y = acc[i][1] + b1;
            o.z = acc[i][2] + b2; o.w = acc[i][3] + b3;
            if (ACT) { o.x = silu_f(o.x); o.y = silu_f(o.y); o.z = silu_f(o.z); o.w = silu_f(o.w); }
            ((float4*)out)[(size_t)row * 16 + tx] = o;
        }
    }
}

__global__ void xupd_kernel(const float* __restrict__ x, const float* __restrict__ xacc,
                            float* __restrict__ out, int n3)
{
    int i = blockIdx.x * blockDim.x + threadIdx.x;
    if (i < n3) out[i] = x[i] + xacc[i];
}

// ------------------- launch -------------------
extern "C" void kernel_launch(void* const* d_in, const int* in_sizes, int n_in,
                              void* d_out, int out_size)
{
    const float* h0  = (const float*)d_in[0];
    const float* x0  = (const float*)d_in[1];
    const int*   src = (const int*)d_in[2];
    const int*   dst = (const int*)d_in[3];
    const float* ew1 = (const float*)d_in[4];
    const float* eb1 = (const float*)d_in[5];
    const float* ew2 = (const float*)d_in[6];
    const float* eb2 = (const float*)d_in[7];
    const float* nw1 = (const float*)d_in[8];
    const float* nb1 = (const float*)d_in[9];
    const float* nw2 = (const float*)d_in[10];
    const float* nb2 = (const float*)d_in[11];
    const float* cw1 = (const float*)d_in[12];
    const float* cb1 = (const float*)d_in[13];
    const float* cw2 = (const float*)d_in[14];

    int n = in_sizes[0] / 64;
    int E = in_sizes[2];

    float *P, *hA, *xA, *hacc, *xacc, *tb, *mbuf;
    int *deg, *off, *woff, *bsum, *bscan, *eidx;
    __half *wh, *wl;
    cudaGetSymbolAddress((void**)&P,    g_P);
    cudaGetSymbolAddress((void**)&hA,   g_hbuf);
    cudaGetSymbolAddress((void**)&xA,   g_xbuf);
    cudaGetSymbolAddress((void**)&hacc, g_hacc);
    cudaGetSymbolAddress((void**)&xacc, g_xacc);
    cudaGetSymbolAddress((void**)&tb,   g_t);
    cudaGetSymbolAddress((void**)&mbuf, g_m);
    cudaGetSymbolAddress((void**)&deg,  g_deg);
    cudaGetSymbolAddress((void**)&off,  g_off);
    cudaGetSymbolAddress((void**)&woff, g_woff);
    cudaGetSymbolAddress((void**)&bsum, g_bsum);
    cudaGetSymbolAddress((void**)&bscan,g_bscan);
    cudaGetSymbolAddress((void**)&eidx, g_eidx);
    cudaGetSymbolAddress((void**)&wh,   g_wh);
    cudaGetSymbolAddress((void**)&wl,   g_wl);

    float* hb[2] = { hA, hA + (size_t)NN * 64 };
    float* xb[2] = { xA, xA + (size_t)NN * 3 };

    const int smP  = (64*64 + 64*128) * 4;
    const int smE  = (4 * HW + 2 * HA) * 2 + 960 * 4;
    const int smN1 = (64*128 + 128*64) * 4;
    const int smN2 = (64*64 + 64*64) * 4;
    cudaFuncSetAttribute(gemm_P_kernel, cudaFuncAttributeMaxDynamicSharedMemorySize, smP);
    cudaFuncSetAttribute(edge_kernel<true>,  cudaFuncAttributeMaxDynamicSharedMemorySize, smE);
    cudaFuncSetAttribute(edge_kernel<false>, cudaFuncAttributeMaxDynamicSharedMemorySize, smE);
    cudaFuncSetAttribute(node_gemm_kernel<128, true>,  cudaFuncAttributeMaxDynamicSharedMemorySize, smN1);
    cudaFuncSetAttribute(node_gemm_kernel<64, false>,  cudaFuncAttributeMaxDynamicSharedMemorySize, smN2);

    int nb_rows = (n + 63) / 64;
    int eb_blocks = (E + 127) / 128;
    int scan_nb = (n + 511) / 512;

    // launch order puts edge_kernel(layer 0) at index 3 for ncu
    deg_zero_kernel<<<(n * 3 + 255) / 256, 256>>>(deg, xacc, n);                       // 0
    gemm_P_kernel<<<nb_rows, 256, smP>>>(h0, ew1, P, n);                               // 1
    wsplit_kernel<<<(DEPTH * 2 * 4096 + 255) / 256, 256>>>(ew2, cw1, wh, wl);          // 2

    for (int d = 0; d < DEPTH; d++) {
        const float* hc = d ? hb[(d - 1) & 1] : h0;
        const float* xc = d ? xb[(d - 1) & 1] : x0;
        float* xo = (d == DEPTH - 1) ? (float*)d_out : xb[d & 1];

        if (d) {
            zerox_kernel<<<(n * 3 + 255) / 256, 256>>>(xacc, n * 3);
            gemm_P_kernel<<<nb_rows, 256, smP>>>(hc, ew1 + (size_t)d * 129 * 64, P, n);
        }

        const __half* w1h = wh + (size_t)(2 * d) * 4096;
        const __half* w1l = wl + (size_t)(2 * d) * 4096;
        const __half* w2h = wh + (size_t)(2 * d + 1) * 4096;
        const __half* w2l = wl + (size_t)(2 * d + 1) * 4096;
        const float* wrp = ew1 + (size_t)d * 129 * 64 + 128 * 64;

        if (d < DEPTH - 1) {
            edge_kernel<true><<<eb_blocks, 256, smE>>>(
                src, dst, xc, P, wrp, eb1 + d * 64,
                w1h, w1l, eb2 + d * 64, w2h, w2l,
                cb1 + d * 64, cw2 + d * 64, mbuf, xacc, E);               // layer0: idx 3

            if (d == 0) {
                deg_count_kernel<<<(E + 255) / 256, 256>>>(dst, deg, E);
                scan_blocks_kernel<<<scan_nb, 512>>>(deg, off, bsum, n);
                scan_bsums_kernel<<<1, 32>>>(bsum, bscan, scan_nb);
                scan_add_kernel<<<(n + 255) / 256, 256>>>(off, bscan, woff, n, E);
                fill_eidx_kernel<<<(E + 255) / 256, 256>>>(dst, woff, eidx, E);
            }

            gather_kernel<<<(n * 32 + 255) / 256, 256>>>(mbuf, off, eidx, hacc, n);

            node_gemm_kernel<128, true><<<nb_rows, 256, smN1>>>(
                hc, hacc, nw1 + (size_t)d * 128 * 64, nb1 + d * 64, tb, n);
            node_gemm_kernel<64, false><<<nb_rows, 256, smN2>>>(
                tb, tb, nw2 + (size_t)d * 4096, nb2 + d * 64, hb[d & 1], n);
        } else {
            edge_kernel<false><<<eb_blocks, 256, smE>>>(
                src, dst, xc, P, wrp, eb1 + d * 64,
                w1h, w1l, eb2 + d * 64, w2h, w2l,
                cb1 + d * 64, cw2 + d * 64, mbuf, xacc, E);
        }

        xupd_kernel<<<(n * 3 + 255) / 256, 256>>>(xc, xacc, xo, n * 3);
    }
}

// round 8
// speedup vs baseline: 1.9154x; 1.0220x over previous
#include <cuda_runtime.h>
#include <cuda_fp16.h>
#include <math.h>

#define NN 100000
#define EE 1600000
#define DEPTH 4

typedef unsigned int u32;

// ------------------- scratch (device globals; no runtime allocs) -------------------
__device__ float g_P[(size_t)NN * 128];
__device__ float g_hbuf[2][(size_t)NN * 64];
__device__ float g_xbuf[2][(size_t)NN * 3];
__device__ float g_hacc[(size_t)NN * 64];
__device__ float g_xacc[(size_t)NN * 3];
__device__ float g_t[(size_t)NN * 64];
__device__ float g_m[(size_t)EE * 64];
__device__ int   g_deg[NN];
__device__ int   g_off[NN + 1];
__device__ int   g_woff[NN];
__device__ int   g_bsum[256];
__device__ int   g_bscan[256];
__device__ int   g_eidx[EE];
__device__ __half g_wh[DEPTH * 2 * 4096];   // [d][0=ew2,1=cw1][4096] hi halves
__device__ __half g_wl[DEPTH * 2 * 4096];   // lo halves

// ------------------- helpers -------------------
__device__ __forceinline__ float silu_f(float v) {
    return __fdividef(v, 1.0f + __expf(-v));
}
__device__ __forceinline__ void red1(float* p, float a) {
    asm volatile("red.global.add.f32 [%0], %1;" :: "l"(p), "f"(a) : "memory");
}
__device__ __forceinline__ u32 smaddr(const void* p) {
    return (u32)__cvta_generic_to_shared(p);
}
__device__ __forceinline__ void ldsm4(u32* r, const void* p) {
    u32 a = smaddr(p);
    asm volatile("ldmatrix.sync.aligned.m8n8.x4.shared.b16 {%0,%1,%2,%3}, [%4];"
                 : "=r"(r[0]), "=r"(r[1]), "=r"(r[2]), "=r"(r[3]) : "r"(a));
}
__device__ __forceinline__ void ldsm4t(u32* r, const void* p) {
    u32 a = smaddr(p);
    asm volatile("ldmatrix.sync.aligned.m8n8.x4.trans.shared.b16 {%0,%1,%2,%3}, [%4];"
                 : "=r"(r[0]), "=r"(r[1]), "=r"(r[2]), "=r"(r[3]) : "r"(a));
}
__device__ __forceinline__ void mma16816(float* c, const u32* a, u32 b0, u32 b1) {
    asm volatile("mma.sync.aligned.m16n8k16.row.col.f32.f16.f16.f32 "
                 "{%0,%1,%2,%3}, {%4,%5,%6,%7}, {%8,%9}, {%0,%1,%2,%3};"
                 : "+f"(c[0]), "+f"(c[1]), "+f"(c[2]), "+f"(c[3])
                 : "r"(a[0]), "r"(a[1]), "r"(a[2]), "r"(a[3]), "r"(b0), "r"(b1));
}
__device__ __forceinline__ void split1(float v, __half& h, __half& l) {
    h = __float2half_rn(v);
    l = __float2half_rn(v - __half2float(h));
}
__device__ __forceinline__ u32 packh2(__half a, __half b) {
    __half2 h = __halves2half2(a, b);
    return *(u32*)&h;
}

// ------------------- weight pre-split -------------------
__global__ void wsplit_kernel(const float* __restrict__ ew2, const float* __restrict__ cw1,
                              __half* __restrict__ wh, __half* __restrict__ wl) {
    int i = blockIdx.x * blockDim.x + threadIdx.x;   // over DEPTH*2*4096
    if (i >= DEPTH * 2 * 4096) return;
    int d = i >> 13, which = (i >> 12) & 1, k = i & 4095;
    float v = which ? cw1[d * 4096 + k] : ew2[d * 4096 + k];
    __half h, l; split1(v, h, l);
    wh[i] = h; wl[i] = l;
}

// ------------------- CSR build -------------------
__global__ void deg_zero_kernel(int* __restrict__ deg, float* __restrict__ xacc, int n) {
    int i = blockIdx.x * blockDim.x + threadIdx.x;
    if (i < n) deg[i] = 0;
    if (i < n * 3) xacc[i] = 0.f;
}
__global__ void deg_count_kernel(const int* __restrict__ dst, int* __restrict__ deg, int E) {
    int e = blockIdx.x * blockDim.x + threadIdx.x;
    if (e < E) atomicAdd(&deg[dst[e]], 1);
}
__global__ void scan_blocks_kernel(const int* __restrict__ deg, int* __restrict__ off,
                                   int* __restrict__ bsum, int n) {
    __shared__ int s[512];
    int tid = threadIdx.x;
    int i = blockIdx.x * 512 + tid;
    int v = (i < n) ? deg[i] : 0;
    s[tid] = v;
    __syncthreads();
    for (int d = 1; d < 512; d <<= 1) {
        int t2 = (tid >= d) ? s[tid - d] : 0;
        __syncthreads();
        s[tid] += t2;
        __syncthreads();
    }
    if (i < n) off[i] = s[tid] - v;
    if (tid == 511) bsum[blockIdx.x] = s[511];
}
__global__ void scan_bsums_kernel(const int* __restrict__ bsum, int* __restrict__ bscan, int nb) {
    if (threadIdx.x == 0 && blockIdx.x == 0) {
        int acc = 0;
        for (int b = 0; b < nb; b++) { bscan[b] = acc; acc += bsum[b]; }
    }
}
__global__ void scan_add_kernel(int* __restrict__ off, const int* __restrict__ bscan,
                                int* __restrict__ woff, int n, int Etot) {
    int i = blockIdx.x * blockDim.x + threadIdx.x;
    if (i < n) {
        int v = off[i] + bscan[i >> 9];
        off[i] = v;
        woff[i] = v;
    }
    if (i == 0) off[n] = Etot;
}
__global__ void fill_eidx_kernel(const int* __restrict__ dst, int* __restrict__ woff,
                                 int* __restrict__ eidx, int E) {
    int e = blockIdx.x * blockDim.x + threadIdx.x;
    if (e < E) {
        int p = atomicAdd(&woff[dst[e]], 1);
        eidx[p] = e;
    }
}
__global__ void zerox_kernel(float* __restrict__ xacc, int n3) {
    int i = blockIdx.x * blockDim.x + threadIdx.x;
    if (i < n3) xacc[i] = 0.f;
}

// ------------------- P = h @ [Wa | Wb] -------------------
__global__ __launch_bounds__(256) void gemm_P_kernel(
    const float* __restrict__ h, const float* __restrict__ ew1,
    float* __restrict__ P, int n)
{
    extern __shared__ float sm[];
    float* As = sm;
    float* Ws = sm + 64 * 64;
    int t = threadIdx.x;
    int row0 = blockIdx.x * 64;

    for (int i = t; i < 64 * 64; i += 256) {
        int r = i >> 6, c = i & 63;
        int gr = row0 + r;
        As[i] = (gr < n) ? h[(size_t)gr * 64 + c] : 0.f;
    }
    for (int i = t; i < 64 * 128; i += 256) {
        int k = i >> 7, j = i & 127;
        Ws[i] = (j < 64) ? ew1[k * 64 + j] : ew1[(64 + k) * 64 + (j - 64)];
    }
    __syncthreads();

    int tx = t & 31;
    int ty = t >> 5;
    float acc[8][4];
#pragma unroll
    for (int i = 0; i < 8; i++) { acc[i][0]=0.f; acc[i][1]=0.f; acc[i][2]=0.f; acc[i][3]=0.f; }

    const float4* Wq = (const float4*)Ws;
#pragma unroll 8
    for (int k = 0; k < 64; k++) {
        float4 w = Wq[k * 32 + tx];
#pragma unroll
        for (int i = 0; i < 8; i++) {
            float av = As[(ty * 8 + i) * 64 + k];
            acc[i][0] += av * w.x; acc[i][1] += av * w.y;
            acc[i][2] += av * w.z; acc[i][3] += av * w.w;
        }
    }
#pragma unroll
    for (int i = 0; i < 8; i++) {
        int row = row0 + ty * 8 + i;
        if (row < n) {
            float4 o = make_float4(acc[i][0], acc[i][1], acc[i][2], acc[i][3]);
            ((float4*)P)[(size_t)row * 32 + tx] = o;
        }
    }
}

// ------------------- edge kernel: mma.sync, register fragment reuse, lean B traffic ----
// smem halves: sW1h/sW1l/sW2h [64][72] | sA1h/sA1l [128][72]
// fp32 tail: wr,eb1,eb2,cb1,cw2 (64 ea) | u0,u1,u2,cp (128 ea) | di (128 int)
#define HW  (64 * 72)
#define HA  (128 * 72)
template<bool STORE>
__global__ __launch_bounds__(256, 2) void edge_kernel(
    const int* __restrict__ src, const int* __restrict__ dst,
    const float* __restrict__ x, const float* __restrict__ P,
    const float* __restrict__ wr,  const float* __restrict__ eb1,
    const __half* __restrict__ w1h, const __half* __restrict__ w1l,   // ew2 split
    const float* __restrict__ eb2,
    const __half* __restrict__ w2h, const __half* __restrict__ w2l,   // cw1 split (lo unused)
    const float* __restrict__ cb1, const float* __restrict__ cw2,
    float* __restrict__ mbuf, float* __restrict__ xacc, int E)
{
    extern __shared__ __half S[];
    __half* sW1h = S;
    __half* sW1l = S + HW;
    __half* sW2h = S + 2 * HW;
    __half* sA1h = S + 3 * HW;
    __half* sA1l = S + 3 * HW + HA;
    float*  F    = (float*)(S + 3 * HW + 2 * HA);
    float* s_wr  = F;
    float* s_eb1 = F + 64;
    float* s_eb2 = F + 128;
    float* s_cb1 = F + 192;
    float* s_cw2 = F + 256;
    float* s_u0  = F + 320;
    float* s_u1  = F + 448;
    float* s_u2  = F + 576;
    float* s_cp  = F + 704;
    int*   s_di  = (int*)(F + 832);

    int t = threadIdx.x;
    int lane = t & 31, w = t >> 5;
    int em0 = blockIdx.x * 128;

    // ---- load small arrays + weight splits (once) ----
    if (t < 64) {
        s_wr[t] = wr[t]; s_eb1[t] = eb1[t]; s_eb2[t] = eb2[t];
        s_cb1[t] = cb1[t]; s_cw2[t] = cw2[t];
    }
    {
        u32* d1h = (u32*)sW1h; u32* d1l = (u32*)sW1l;
        u32* d2h = (u32*)sW2h;
        const u32* s1h = (const u32*)w1h; const u32* s1l = (const u32*)w1l;
        const u32* s2h = (const u32*)w2h;
#pragma unroll
        for (int i = t; i < 2048; i += 256) {
            int row = i >> 5, c2 = i & 31;
            d1h[row * 36 + c2] = s1h[row * 32 + c2];
            d1l[row * 36 + c2] = s1l[row * 32 + c2];
            d2h[row * 36 + c2] = s2h[row * 32 + c2];
        }
    }
    __syncthreads();

    // ---- phase A: m1 = silu(P[src][0:64] + P[dst][64:128] + r*wr + eb1) -> sA1 ----
    {
        int eloc = t >> 1, ht = t & 1;
        int e = em0 + eloc;
        int si = 0, di = 0;
        float r = 0.f, u0 = 0.f, u1 = 0.f, u2 = 0.f;
        if (e < E) {
            si = src[e]; di = dst[e];
            float dx0 = x[si * 3 + 0] - x[di * 3 + 0];
            float dx1 = x[si * 3 + 1] - x[di * 3 + 1];
            float dx2 = x[si * 3 + 2] - x[di * 3 + 2];
            r = dx0 * dx0 + dx1 * dx1 + dx2 * dx2;
            float inv = __fdividef(1.0f, sqrtf(r) + 1e-30f);
            u0 = dx0 * inv; u1 = dx1 * inv; u2 = dx2 * inv;
        }
        if (ht == 0) {
            s_di[eloc] = di;
            s_u0[eloc] = u0; s_u1[eloc] = u1; s_u2[eloc] = u2;
        }
        const float4* Pa = (const float4*)(P + (size_t)si * 128) + ht * 8;
        const float4* Pb = (const float4*)(P + (size_t)di * 128 + 64) + ht * 8;
        __half* rh = sA1h + eloc * 72 + ht * 32;
        __half* rl = sA1l + eloc * 72 + ht * 32;
#pragma unroll
        for (int i = 0; i < 8; i++) {
            float4 va = Pa[i], vb = Pb[i];
            int f = ht * 32 + 4 * i;
            float v0 = silu_f(va.x + vb.x + r * s_wr[f+0] + s_eb1[f+0]);
            float v1 = silu_f(va.y + vb.y + r * s_wr[f+1] + s_eb1[f+1]);
            float v2 = silu_f(va.z + vb.z + r * s_wr[f+2] + s_eb1[f+2]);
            float v3 = silu_f(va.w + vb.w + r * s_wr[f+3] + s_eb1[f+3]);
            __half h0,h1,h2,h3,l0,l1,l2,l3;
            split1(v0,h0,l0); split1(v1,h1,l1); split1(v2,h2,l2); split1(v3,h3,l3);
            *(__half2*)(rh + 4*i)     = __halves2half2(h0, h1);
            *(__half2*)(rh + 4*i + 2) = __halves2half2(h2, h3);
            *(__half2*)(rl + 4*i)     = __halves2half2(l0, l1);
            *(__half2*)(rl + 4*i + 2) = __halves2half2(l2, l3);
        }
    }
    __syncthreads();

    // ---- GEMM1: m = silu(m1 @ ew2 + eb2), 3-pass split ----
    u32 Ah[16], Al[16];
#pragma unroll
    for (int ks = 0; ks < 4; ks++) {
        const __half* pa = sA1h + (16 * w + (lane & 15)) * 72 + 16 * ks + 8 * (lane >> 4);
        const __half* pl = sA1l + (16 * w + (lane & 15)) * 72 + 16 * ks + 8 * (lane >> 4);
        ldsm4(&Ah[4 * ks], pa);
        ldsm4(&Al[4 * ks], pl);
    }

    u32 A2h[16], A2l[16];
    int row = 16 * w + (lane >> 2);
#pragma unroll
    for (int ntp = 0; ntp < 4; ntp++) {
        float acc0[4] = {0.f, 0.f, 0.f, 0.f};
        float acc1[4] = {0.f, 0.f, 0.f, 0.f};
#pragma unroll
        for (int ks = 0; ks < 4; ks++) {
            u32 bh[4], bl[4];
            // x4 trans: lanes 0-15 -> nt=2ntp (mats 0,1), lanes 16-31 -> nt=2ntp+1 (mats 2,3)
            const __half* ph = sW1h + (16 * ks + (lane & 15)) * 72 + 8 * (2 * ntp + (lane >> 4));
            const __half* pl = sW1l + (16 * ks + (lane & 15)) * 72 + 8 * (2 * ntp + (lane >> 4));
            ldsm4t(bh, ph);
            ldsm4t(bl, pl);
            mma16816(acc0, &Ah[4 * ks], bh[0], bh[1]);
            mma16816(acc0, &Ah[4 * ks], bl[0], bl[1]);
            mma16816(acc0, &Al[4 * ks], bh[0], bh[1]);
            mma16816(acc1, &Ah[4 * ks], bh[2], bh[3]);
            mma16816(acc1, &Ah[4 * ks], bl[2], bl[3]);
            mma16816(acc1, &Al[4 * ks], bh[2], bh[3]);
        }
        // epilogue for nt=2ntp (acc0) and nt=2ntp+1 (acc1)
#pragma unroll
        for (int s = 0; s < 2; s++) {
            float* acc = s ? acc1 : acc0;
            int nt = 2 * ntp + s;
            int col = 8 * nt + 2 * (lane & 3);
            float m0 = silu_f(acc[0] + s_eb2[col]);
            float m1 = silu_f(acc[1] + s_eb2[col + 1]);
            float m2 = silu_f(acc[2] + s_eb2[col]);
            float m3 = silu_f(acc[3] + s_eb2[col + 1]);
            if (STORE) {
                int e0 = em0 + row, e1 = em0 + row + 8;
                if (e0 < E) { float2 o; o.x = m0; o.y = m1; *(float2*)(mbuf + (size_t)e0 * 64 + col) = o; }
                if (e1 < E) { float2 o; o.x = m2; o.y = m3; *(float2*)(mbuf + (size_t)e1 * 64 + col) = o; }
            }
            __half h0,h1,h2,h3,l0,l1,l2,l3;
            split1(m0,h0,l0); split1(m1,h1,l1); split1(m2,h2,l2); split1(m3,h3,l3);
            int base = 4 * (nt >> 1) + 2 * (nt & 1);
            A2h[base + 0] = packh2(h0, h1);
            A2h[base + 1] = packh2(h2, h3);
            A2l[base + 0] = packh2(l0, l1);
            A2l[base + 1] = packh2(l2, l3);
        }
    }

    // ---- GEMM2 (2-pass: A-split exact, cw1 quantized to fp16): c1 = silu(m @ cw1h + cb1) ----
    float rs0 = 0.f, rs1 = 0.f;
#pragma unroll
    for (int ntp = 0; ntp < 4; ntp++) {
        float acc0[4] = {0.f, 0.f, 0.f, 0.f};
        float acc1[4] = {0.f, 0.f, 0.f, 0.f};
#pragma unroll
        for (int ks = 0; ks < 4; ks++) {
            u32 b[4];
            ldsm4t(b, sW2h + (16 * ks + (lane & 15)) * 72 + 8 * (2 * ntp + (lane >> 4)));
            mma16816(acc0, &A2h[4 * ks], b[0], b[1]);
            mma16816(acc0, &A2l[4 * ks], b[0], b[1]);
            mma16816(acc1, &A2h[4 * ks], b[2], b[3]);
            mma16816(acc1, &A2l[4 * ks], b[2], b[3]);
        }
#pragma unroll
        for (int s = 0; s < 2; s++) {
            float* acc = s ? acc1 : acc0;
            int col = 8 * (2 * ntp + s) + 2 * (lane & 3);
            rs0 += silu_f(acc[0] + s_cb1[col]) * s_cw2[col]
                 + silu_f(acc[1] + s_cb1[col + 1]) * s_cw2[col + 1];
            rs1 += silu_f(acc[2] + s_cb1[col]) * s_cw2[col]
                 + silu_f(acc[3] + s_cb1[col + 1]) * s_cw2[col + 1];
        }
    }
    rs0 += __shfl_xor_sync(0xffffffffu, rs0, 1);
    rs0 += __shfl_xor_sync(0xffffffffu, rs0, 2);
    rs1 += __shfl_xor_sync(0xffffffffu, rs1, 1);
    rs1 += __shfl_xor_sync(0xffffffffu, rs1, 2);
    if ((lane & 3) == 0) {
        s_cp[16 * w + (lane >> 2)]     = rs0;
        s_cp[16 * w + 8 + (lane >> 2)] = rs1;
    }
    __syncthreads();

    if (t < 128) {
        int e = em0 + t;
        if (e < E) {
            float c = s_cp[t];
            int di = s_di[t];
            float* xp = xacc + (size_t)di * 3;
            red1(xp + 0, c * s_u0[t]);
            red1(xp + 1, c * s_u1[t]);
            red1(xp + 2, c * s_u2[t]);
        }
    }
}

// ------------------- gather -------------------
__global__ void gather_kernel(const float* __restrict__ m, const int* __restrict__ off,
                              const int* __restrict__ eidx, float* __restrict__ hn, int n)
{
    int warp = (blockIdx.x * blockDim.x + threadIdx.x) >> 5;
    int lane = threadIdx.x & 31;
    if (warp >= n) return;
    int b = off[warp], en = off[warp + 1];
    float ax = 0.f, ay = 0.f;
    for (int i = b; i < en; i++) {
        int eid = eidx[i];
        float2 v = ((const float2*)(m + (size_t)eid * 64))[lane];
        ax += v.x; ay += v.y;
    }
    float2 o; o.x = ax; o.y = ay;
    ((float2*)(hn + (size_t)warp * 64))[lane] = o;
}

// ------------------- node GEMM -------------------
template<int K, bool ACT>
__global__ __launch_bounds__(256) void node_gemm_kernel(
    const float* __restrict__ A1, const float* __restrict__ A2,
    const float* __restrict__ W, const float* __restrict__ bias,
    float* __restrict__ out, int n)
{
    extern __shared__ float sm[];
    float* As = sm;
    float* Ws = sm + 64 * K;
    int t = threadIdx.x;
    int row0 = blockIdx.x * 64;

    for (int i = t; i < 64 * K; i += 256) {
        int r = i / K, c = i % K;
        int gr = row0 + r;
        float v = 0.f;
        if (gr < n) {
            if (K == 64 || c < 64) v = A1[(size_t)gr * 64 + (c & 63)];
            else                   v = A2[(size_t)gr * 64 + (c - 64)];
        }
        As[i] = v;
    }
    for (int i = t; i < K * 64; i += 256) Ws[i] = W[i];
    __syncthreads();

    int tx = t & 15;
    int ty = t >> 4;
    float acc[4][4];
#pragma unroll
    for (int i = 0; i < 4; i++) { acc[i][0]=0.f; acc[i][1]=0.f; acc[i][2]=0.f; acc[i][3]=0.f; }

    const float4* Wq = (const float4*)Ws;
#pragma unroll 8
    for (int k = 0; k < K; k++) {
        float4 w = Wq[k * 16 + tx];
#pragma unroll
        for (int i = 0; i < 4; i++) {
            float av = As[(ty * 4 + i) * K + k];
            acc[i][0] += av * w.x; acc[i][1] += av * w.y;
            acc[i][2] += av * w.z; acc[i][3] += av * w.w;
        }
    }

    float b0 = bias[tx*4+0], b1 = bias[tx*4+1], b2 = bias[tx*4+2], b3 = bias[tx*4+3];
#pragma unroll
    for (int i = 0; i < 4; i++) {
        int row = row0 + ty * 4 + i;
        if (row < n) {
            float4 o;
            o.x = acc[i][0] + b0; o.y = acc[i][1] + b1;
            o.z = acc[i][2] + b2; o.w = acc[i][3] + b3;
            if (ACT) { o.x = silu_f(o.x); o.y = silu_f(o.y); o.z = silu_f(o.z); o.w = silu_f(o.w); }
            ((float4*)out)[(size_t)row * 16 + tx] = o;
        }
    }
}

__global__ void xupd_kernel(const float* __restrict__ x, const float* __restrict__ xacc,
                            float* __restrict__ out, int n3)
{
    int i = blockIdx.x * blockDim.x + threadIdx.x;
    if (i < n3) out[i] = x[i] + xacc[i];
}

// ------------------- launch -------------------
extern "C" void kernel_launch(void* const* d_in, const int* in_sizes, int n_in,
                              void* d_out, int out_size)
{
    const float* h0  = (const float*)d_in[0];
    const float* x0  = (const float*)d_in[1];
    const int*   src = (const int*)d_in[2];
    const int*   dst = (const int*)d_in[3];
    const float* ew1 = (const float*)d_in[4];
    const float* eb1 = (const float*)d_in[5];
    const float* ew2 = (const float*)d_in[6];
    const float* eb2 = (const float*)d_in[7];
    const float* nw1 = (const float*)d_in[8];
    const float* nb1 = (const float*)d_in[9];
    const float* nw2 = (const float*)d_in[10];
    const float* nb2 = (const float*)d_in[11];
    const float* cw1 = (const float*)d_in[12];
    const float* cb1 = (const float*)d_in[13];
    const float* cw2 = (const float*)d_in[14];

    int n = in_sizes[0] / 64;
    int E = in_sizes[2];

    float *P, *hA, *xA, *hacc, *xacc, *tb, *mbuf;
    int *deg, *off, *woff, *bsum, *bscan, *eidx;
    __half *wh, *wl;
    cudaGetSymbolAddress((void**)&P,    g_P);
    cudaGetSymbolAddress((void**)&hA,   g_hbuf);
    cudaGetSymbolAddress((void**)&xA,   g_xbuf);
    cudaGetSymbolAddress((void**)&hacc, g_hacc);
    cudaGetSymbolAddress((void**)&xacc, g_xacc);
    cudaGetSymbolAddress((void**)&tb,   g_t);
    cudaGetSymbolAddress((void**)&mbuf, g_m);
    cudaGetSymbolAddress((void**)&deg,  g_deg);
    cudaGetSymbolAddress((void**)&off,  g_off);
    cudaGetSymbolAddress((void**)&woff, g_woff);
    cudaGetSymbolAddress((void**)&bsum, g_bsum);
    cudaGetSymbolAddress((void**)&bscan,g_bscan);
    cudaGetSymbolAddress((void**)&eidx, g_eidx);
    cudaGetSymbolAddress((void**)&wh,   g_wh);
    cudaGetSymbolAddress((void**)&wl,   g_wl);

    float* hb[2] = { hA, hA + (size_t)NN * 64 };
    float* xb[2] = { xA, xA + (size_t)NN * 3 };

    const int smP  = (64*64 + 64*128) * 4;
    const int smE  = (3 * HW + 2 * HA) * 2 + 960 * 4;
    const int smN1 = (64*128 + 128*64) * 4;
    const int smN2 = (64*64 + 64*64) * 4;
    cudaFuncSetAttribute(gemm_P_kernel, cudaFuncAttributeMaxDynamicSharedMemorySize, smP);
    cudaFuncSetAttribute(edge_kernel<true>,  cudaFuncAttributeMaxDynamicSharedMemorySize, smE);
    cudaFuncSetAttribute(edge_kernel<false>, cudaFuncAttributeMaxDynamicSharedMemorySize, smE);
    cudaFuncSetAttribute(node_gemm_kernel<128, true>,  cudaFuncAttributeMaxDynamicSharedMemorySize, smN1);
    cudaFuncSetAttribute(node_gemm_kernel<64, false>,  cudaFuncAttributeMaxDynamicSharedMemorySize, smN2);

    int nb_rows = (n + 63) / 64;
    int eb_blocks = (E + 127) / 128;
    int scan_nb = (n + 511) / 512;

    // launch order puts edge_kernel(layer 0) at index 3 for ncu
    deg_zero_kernel<<<(n * 3 + 255) / 256, 256>>>(deg, xacc, n);                       // 0
    gemm_P_kernel<<<nb_rows, 256, smP>>>(h0, ew1, P, n);                               // 1
    wsplit_kernel<<<(DEPTH * 2 * 4096 + 255) / 256, 256>>>(ew2, cw1, wh, wl);          // 2

    for (int d = 0; d < DEPTH; d++) {
        const float* hc = d ? hb[(d - 1) & 1] : h0;
        const float* xc = d ? xb[(d - 1) & 1] : x0;
        float* xo = (d == DEPTH - 1) ? (float*)d_out : xb[d & 1];

        if (d) {
            zerox_kernel<<<(n * 3 + 255) / 256, 256>>>(xacc, n * 3);
            gemm_P_kernel<<<nb_rows, 256, smP>>>(hc, ew1 + (size_t)d * 129 * 64, P, n);
        }

        const __half* w1h = wh + (size_t)(2 * d) * 4096;
        const __half* w1l = wl + (size_t)(2 * d) * 4096;
        const __half* w2h = wh + (size_t)(2 * d + 1) * 4096;
        const __half* w2l = wl + (size_t)(2 * d + 1) * 4096;
        const float* wrp = ew1 + (size_t)d * 129 * 64 + 128 * 64;

        if (d < DEPTH - 1) {
            edge_kernel<true><<<eb_blocks, 256, smE>>>(
                src, dst, xc, P, wrp, eb1 + d * 64,
                w1h, w1l, eb2 + d * 64, w2h, w2l,
                cb1 + d * 64, cw2 + d * 64, mbuf, xacc, E);               // layer0: idx 3

            if (d == 0) {
                deg_count_kernel<<<(E + 255) / 256, 256>>>(dst, deg, E);
                scan_blocks_kernel<<<scan_nb, 512>>>(deg, off, bsum, n);
                scan_bsums_kernel<<<1, 32>>>(bsum, bscan, scan_nb);
                scan_add_kernel<<<(n + 255) / 256, 256>>>(off, bscan, woff, n, E);
                fill_eidx_kernel<<<(E + 255) / 256, 256>>>(dst, woff, eidx, E);
            }

            gather_kernel<<<(n * 32 + 255) / 256, 256>>>(mbuf, off, eidx, hacc, n);

            node_gemm_kernel<128, true><<<nb_rows, 256, smN1>>>(
                hc, hacc, nw1 + (size_t)d * 128 * 64, nb1 + d * 64, tb, n);
            node_gemm_kernel<64, false><<<nb_rows, 256, smN2>>>(
                tb, tb, nw2 + (size_t)d * 4096, nb2 + d * 64, hb[d & 1], n);
        } else {
            edge_kernel<false><<<eb_blocks, 256, smE>>>(
                src, dst, xc, P, wrp, eb1 + d * 64,
                w1h, w1l, eb2 + d * 64, w2h, w2l,
                cb1 + d * 64, cw2 + d * 64, mbuf, xacc, E);
        }

        xupd_kernel<<<(n * 3 + 255) / 256, 256>>>(xc, xacc, xo, n * 3);
    }
}

// round 9
// speedup vs baseline: 2.0694x; 1.0804x over previous
#include <cuda_runtime.h>
#include <cuda_fp16.h>
#include <math.h>

#define NN 100000
#define EE 1600000
#define DEPTH 4

typedef unsigned int u32;

// ------------------- scratch (device globals; no runtime allocs) -------------------
__device__ float g_P[(size_t)NN * 128];
__device__ float g_hbuf[2][(size_t)NN * 64];
__device__ float g_xbuf[2][(size_t)NN * 3];
__device__ float g_hacc[(size_t)NN * 64];
__device__ float g_xacc[(size_t)NN * 3];
__device__ float g_t[(size_t)NN * 64];
__device__ float g_m[(size_t)EE * 64];
__device__ int   g_deg[NN];
__device__ int   g_off[NN + 1];
__device__ int   g_woff[NN];
__device__ int   g_bsum[256];
__device__ int   g_bscan[256];
__device__ int   g_eidx[EE];
__device__ float g_zero[128];                 // zero bias (static-zero)
// edge weights [d][which][k(64)][n(64)] hi/lo
__device__ __half g_wh[DEPTH * 2 * 4096];
__device__ __half g_wl[DEPTH * 2 * 4096];
// P-projection weights [d][k(64)][n(128)] hi/lo  (cols: [Wa | Wb])
__device__ __half g_pwh[DEPTH * 8192];
__device__ __half g_pwl[DEPTH * 8192];
// node weights: nw1 [d][k(128)][n(64)], nw2 [d][k(64)][n(64)] hi/lo
__device__ __half g_n1h[DEPTH * 8192];
__device__ __half g_n1l[DEPTH * 8192];
__device__ __half g_n2h[DEPTH * 4096];
__device__ __half g_n2l[DEPTH * 4096];

// ------------------- helpers -------------------
__device__ __forceinline__ float silu_f(float v) {
    return __fdividef(v, 1.0f + __expf(-v));
}
__device__ __forceinline__ void red1(float* p, float a) {
    asm volatile("red.global.add.f32 [%0], %1;" :: "l"(p), "f"(a) : "memory");
}
__device__ __forceinline__ u32 smaddr(const void* p) {
    return (u32)__cvta_generic_to_shared(p);
}
__device__ __forceinline__ void ldsm4(u32* r, const void* p) {
    u32 a = smaddr(p);
    asm volatile("ldmatrix.sync.aligned.m8n8.x4.shared.b16 {%0,%1,%2,%3}, [%4];"
                 : "=r"(r[0]), "=r"(r[1]), "=r"(r[2]), "=r"(r[3]) : "r"(a));
}
__device__ __forceinline__ void ldsm4t(u32* r, const void* p) {
    u32 a = smaddr(p);
    asm volatile("ldmatrix.sync.aligned.m8n8.x4.trans.shared.b16 {%0,%1,%2,%3}, [%4];"
                 : "=r"(r[0]), "=r"(r[1]), "=r"(r[2]), "=r"(r[3]) : "r"(a));
}
__device__ __forceinline__ void mma16816(float* c, const u32* a, u32 b0, u32 b1) {
    asm volatile("mma.sync.aligned.m16n8k16.row.col.f32.f16.f16.f32 "
                 "{%0,%1,%2,%3}, {%4,%5,%6,%7}, {%8,%9}, {%0,%1,%2,%3};"
                 : "+f"(c[0]), "+f"(c[1]), "+f"(c[2]), "+f"(c[3])
                 : "r"(a[0]), "r"(a[1]), "r"(a[2]), "r"(a[3]), "r"(b0), "r"(b1));
}
__device__ __forceinline__ void split1(float v, __half& h, __half& l) {
    h = __float2half_rn(v);
    l = __float2half_rn(v - __half2float(h));
}
__device__ __forceinline__ u32 packh2(__half a, __half b) {
    __half2 h = __halves2half2(a, b);
    return *(u32*)&h;
}

// ------------------- weight pre-split: edge (ew2, cw1) -------------------
__global__ void wsplit_kernel(const float* __restrict__ ew2, const float* __restrict__ cw1,
                              __half* __restrict__ wh, __half* __restrict__ wl) {
    int i = blockIdx.x * blockDim.x + threadIdx.x;
    if (i >= DEPTH * 2 * 4096) return;
    int d = i >> 13, which = (i >> 12) & 1, k = i & 4095;
    float v = which ? cw1[d * 4096 + k] : ew2[d * 4096 + k];
    __half h, l; split1(v, h, l);
    wh[i] = h; wl[i] = l;
}

// ------------------- weight pre-split: P / node weights -------------------
__global__ void wsplit2_kernel(const float* __restrict__ ew1, const float* __restrict__ nw1,
                               const float* __restrict__ nw2,
                               __half* __restrict__ pwh, __half* __restrict__ pwl,
                               __half* __restrict__ n1h, __half* __restrict__ n1l,
                               __half* __restrict__ n2h, __half* __restrict__ n2l) {
    int i = blockIdx.x * blockDim.x + threadIdx.x;
    if (i < DEPTH * 8192) {            // P: [d][k(64)][j(128)]
        int d = i >> 13, r = i & 8191;
        int k = r >> 7, j = r & 127;
        float v = ew1[(size_t)d * 129 * 64 + (size_t)((j < 64) ? k : 64 + k) * 64 + (j & 63)];
        __half h, l; split1(v, h, l);
        pwh[i] = h; pwl[i] = l;
    }
    if (i < DEPTH * 8192) {            // n1: straight copy of nw1 [128][64]
        float v = nw1[i];
        __half h, l; split1(v, h, l);
        n1h[i] = h; n1l[i] = l;
    }
    if (i < DEPTH * 4096) {            // n2: straight copy of nw2 [64][64]
        float v = nw2[i];
        __half h, l; split1(v, h, l);
        n2h[i] = h; n2l[i] = l;
    }
}

// ------------------- CSR build -------------------
__global__ void deg_zero_kernel(int* __restrict__ deg, float* __restrict__ xacc, int n) {
    int i = blockIdx.x * blockDim.x + threadIdx.x;
    if (i < n) deg[i] = 0;
    if (i < n * 3) xacc[i] = 0.f;
}
__global__ void deg_count_kernel(const int* __restrict__ dst, int* __restrict__ deg, int E) {
    int e = blockIdx.x * blockDim.x + threadIdx.x;
    if (e < E) atomicAdd(&deg[dst[e]], 1);
}
__global__ void scan_blocks_kernel(const int* __restrict__ deg, int* __restrict__ off,
                                   int* __restrict__ bsum, int n) {
    __shared__ int s[512];
    int tid = threadIdx.x;
    int i = blockIdx.x * 512 + tid;
    int v = (i < n) ? deg[i] : 0;
    s[tid] = v;
    __syncthreads();
    for (int d = 1; d < 512; d <<= 1) {
        int t2 = (tid >= d) ? s[tid - d] : 0;
        __syncthreads();
        s[tid] += t2;
        __syncthreads();
    }
    if (i < n) off[i] = s[tid] - v;
    if (tid == 511) bsum[blockIdx.x] = s[511];
}
__global__ void scan_bsums_kernel(const int* __restrict__ bsum, int* __restrict__ bscan, int nb) {
    if (threadIdx.x == 0 && blockIdx.x == 0) {
        int acc = 0;
        for (int b = 0; b < nb; b++) { bscan[b] = acc; acc += bsum[b]; }
    }
}
__global__ void scan_add_kernel(int* __restrict__ off, const int* __restrict__ bscan,
                                int* __restrict__ woff, int n, int Etot) {
    int i = blockIdx.x * blockDim.x + threadIdx.x;
    if (i < n) {
        int v = off[i] + bscan[i >> 9];
        off[i] = v;
        woff[i] = v;
    }
    if (i == 0) off[n] = Etot;
}
__global__ void fill_eidx_kernel(const int* __restrict__ dst, int* __restrict__ woff,
                                 int* __restrict__ eidx, int E) {
    int e = blockIdx.x * blockDim.x + threadIdx.x;
    if (e < E) {
        int p = atomicAdd(&woff[dst[e]], 1);
        eidx[p] = e;
    }
}
__global__ void zerox_kernel(float* __restrict__ xacc, int n3) {
    int i = blockIdx.x * blockDim.x + threadIdx.x;
    if (i < n3) xacc[i] = 0.f;
}

// ------------------- generic split-fp16 tensor GEMM: out = act(A @ W + b) -------------------
// A = [A1 | A2] rows (64-wide each when K=128), W stored [K rows][N cols] row-major (hi/lo split)
template<int K, int N, bool ACT>
__global__ __launch_bounds__(128) void tgemm_kernel(
    const float* __restrict__ A1, const float* __restrict__ A2,
    const __half* __restrict__ wh, const __half* __restrict__ wl,
    const float* __restrict__ bias, float* __restrict__ out, int n)
{
    constexpr int SA = K + 8;
    constexpr int SW = N + 8;
    extern __shared__ __half S[];
    __half* sAh = S;
    __half* sAl = S + 64 * SA;
    __half* sWh = S + 2 * 64 * SA;
    __half* sWl = sWh + K * SW;
    float*  s_b = (float*)(sWl + K * SW);

    int t = threadIdx.x, lane = t & 31, w = t >> 5;
    int row0 = blockIdx.x * 64;

    if (t < N) s_b[t] = bias[t];

    // load + split A (64 rows x K)
    for (int idx = t; idx < 64 * (K / 4); idx += 128) {
        int r = idx / (K / 4), c4 = idx % (K / 4);
        int gr = row0 + r;
        float4 v = make_float4(0.f, 0.f, 0.f, 0.f);
        if (gr < n) {
            int c = 4 * c4;
            if (K == 64 || c < 64) v = *(const float4*)(A1 + (size_t)gr * 64 + (c & 63));
            else                   v = *(const float4*)(A2 + (size_t)gr * 64 + (c - 64));
        }
        __half h0,h1,h2,h3,l0,l1,l2,l3;
        split1(v.x,h0,l0); split1(v.y,h1,l1); split1(v.z,h2,l2); split1(v.w,h3,l3);
        *(__half2*)(sAh + r * SA + 4 * c4)     = __halves2half2(h0, h1);
        *(__half2*)(sAh + r * SA + 4 * c4 + 2) = __halves2half2(h2, h3);
        *(__half2*)(sAl + r * SA + 4 * c4)     = __halves2half2(l0, l1);
        *(__half2*)(sAl + r * SA + 4 * c4 + 2) = __halves2half2(l2, l3);
    }
    // load W splits (K rows x N)
    for (int idx = t; idx < K * (N / 2); idx += 128) {
        int r = idx / (N / 2), c2 = idx % (N / 2);
        ((u32*)(sWh + r * SW))[c2] = ((const u32*)(wh + (size_t)r * N))[c2];
        ((u32*)(sWl + r * SW))[c2] = ((const u32*)(wl + (size_t)r * N))[c2];
    }
    __syncthreads();

    u32 Ah[K / 4], Al[K / 4];
#pragma unroll
    for (int ks = 0; ks < K / 16; ks++) {
        ldsm4(&Ah[4*ks], sAh + (16*w + (lane & 15)) * SA + 16*ks + 8*(lane >> 4));
        ldsm4(&Al[4*ks], sAl + (16*w + (lane & 15)) * SA + 16*ks + 8*(lane >> 4));
    }
    int row = 16 * w + (lane >> 2);
#pragma unroll
    for (int ntp = 0; ntp < N / 16; ntp++) {
        float acc0[4] = {0.f,0.f,0.f,0.f};
        float acc1[4] = {0.f,0.f,0.f,0.f};
#pragma unroll
        for (int ks = 0; ks < K / 16; ks++) {
            u32 bh[4], bl[4];
            ldsm4t(bh, sWh + (16*ks + (lane & 15)) * SW + 8*(2*ntp + (lane >> 4)));
            ldsm4t(bl, sWl + (16*ks + (lane & 15)) * SW + 8*(2*ntp + (lane >> 4)));
            mma16816(acc0, &Ah[4*ks], bh[0], bh[1]);
            mma16816(acc0, &Ah[4*ks], bl[0], bl[1]);
            mma16816(acc0, &Al[4*ks], bh[0], bh[1]);
            mma16816(acc1, &Ah[4*ks], bh[2], bh[3]);
            mma16816(acc1, &Ah[4*ks], bl[2], bl[3]);
            mma16816(acc1, &Al[4*ks], bh[2], bh[3]);
        }
#pragma unroll
        for (int s = 0; s < 2; s++) {
            float* acc = s ? acc1 : acc0;
            int col = 8 * (2*ntp + s) + 2 * (lane & 3);
            float o0 = acc[0] + s_b[col],   o1 = acc[1] + s_b[col+1];
            float o2 = acc[2] + s_b[col],   o3 = acc[3] + s_b[col+1];
            if (ACT) { o0=silu_f(o0); o1=silu_f(o1); o2=silu_f(o2); o3=silu_f(o3); }
            int g0 = row0 + row, g1 = row0 + row + 8;
            if (g0 < n) { float2 v; v.x=o0; v.y=o1; *(float2*)(out + (size_t)g0 * N + col) = v; }
            if (g1 < n) { float2 v; v.x=o2; v.y=o3; *(float2*)(out + (size_t)g1 * N + col) = v; }
        }
    }
}

// ------------------- edge kernel: mma.sync, fragment reuse, 3-pass both GEMMs ----
// smem halves: sW1h/sW1l/sW2h/sW2l [64][72] | sA1h/sA1l [128][72]
#define HW  (64 * 72)
#define HA  (128 * 72)
template<bool STORE>
__global__ __launch_bounds__(256, 2) void edge_kernel(
    const int* __restrict__ src, const int* __restrict__ dst,
    const float* __restrict__ x, const float* __restrict__ P,
    const float* __restrict__ wr,  const float* __restrict__ eb1,
    const __half* __restrict__ w1h, const __half* __restrict__ w1l,
    const float* __restrict__ eb2,
    const __half* __restrict__ w2h, const __half* __restrict__ w2l,
    const float* __restrict__ cb1, const float* __restrict__ cw2,
    float* __restrict__ mbuf, float* __restrict__ xacc, int E)
{
    extern __shared__ __half S[];
    __half* sW1h = S;
    __half* sW1l = S + HW;
    __half* sW2h = S + 2 * HW;
    __half* sW2l = S + 3 * HW;
    __half* sA1h = S + 4 * HW;
    __half* sA1l = S + 4 * HW + HA;
    float*  F    = (float*)(S + 4 * HW + 2 * HA);
    float* s_wr  = F;
    float* s_eb1 = F + 64;
    float* s_eb2 = F + 128;
    float* s_cb1 = F + 192;
    float* s_cw2 = F + 256;
    float* s_u0  = F + 320;
    float* s_u1  = F + 448;
    float* s_u2  = F + 576;
    float* s_cp  = F + 704;
    int*   s_di  = (int*)(F + 832);

    int t = threadIdx.x;
    int lane = t & 31, w = t >> 5;
    int em0 = blockIdx.x * 128;

    if (t < 64) {
        s_wr[t] = wr[t]; s_eb1[t] = eb1[t]; s_eb2[t] = eb2[t];
        s_cb1[t] = cb1[t]; s_cw2[t] = cw2[t];
    }
    {
        u32* d1h = (u32*)sW1h; u32* d1l = (u32*)sW1l;
        u32* d2h = (u32*)sW2h; u32* d2l = (u32*)sW2l;
        const u32* s1h = (const u32*)w1h; const u32* s1l = (const u32*)w1l;
        const u32* s2h = (const u32*)w2h; const u32* s2l = (const u32*)w2l;
#pragma unroll
        for (int i = t; i < 2048; i += 256) {
            int row = i >> 5, c2 = i & 31;
            d1h[row * 36 + c2] = s1h[row * 32 + c2];
            d1l[row * 36 + c2] = s1l[row * 32 + c2];
            d2h[row * 36 + c2] = s2h[row * 32 + c2];
            d2l[row * 36 + c2] = s2l[row * 32 + c2];
        }
    }
    __syncthreads();

    // ---- phase A: m1 = silu(P[src][0:64] + P[dst][64:128] + r*wr + eb1) -> sA1 ----
    {
        int eloc = t >> 1, ht = t & 1;
        int e = em0 + eloc;
        int si = 0, di = 0;
        float r = 0.f, u0 = 0.f, u1 = 0.f, u2 = 0.f;
        if (e < E) {
            si = src[e]; di = dst[e];
            float dx0 = x[si * 3 + 0] - x[di * 3 + 0];
            float dx1 = x[si * 3 + 1] - x[di * 3 + 1];
            float dx2 = x[si * 3 + 2] - x[di * 3 + 2];
            r = dx0 * dx0 + dx1 * dx1 + dx2 * dx2;
            float inv = __fdividef(1.0f, sqrtf(r) + 1e-30f);
            u0 = dx0 * inv; u1 = dx1 * inv; u2 = dx2 * inv;
        }
        if (ht == 0) {
            s_di[eloc] = di;
            s_u0[eloc] = u0; s_u1[eloc] = u1; s_u2[eloc] = u2;
        }
        const float4* Pa = (const float4*)(P + (size_t)si * 128) + ht * 8;
        const float4* Pb = (const float4*)(P + (size_t)di * 128 + 64) + ht * 8;
        __half* rh = sA1h + eloc * 72 + ht * 32;
        __half* rl = sA1l + eloc * 72 + ht * 32;
#pragma unroll
        for (int i = 0; i < 8; i++) {
            float4 va = Pa[i], vb = Pb[i];
            int f = ht * 32 + 4 * i;
            float v0 = silu_f(va.x + vb.x + r * s_wr[f+0] + s_eb1[f+0]);
            float v1 = silu_f(va.y + vb.y + r * s_wr[f+1] + s_eb1[f+1]);
            float v2 = silu_f(va.z + vb.z + r * s_wr[f+2] + s_eb1[f+2]);
            float v3 = silu_f(va.w + vb.w + r * s_wr[f+3] + s_eb1[f+3]);
            __half h0,h1,h2,h3,l0,l1,l2,l3;
            split1(v0,h0,l0); split1(v1,h1,l1); split1(v2,h2,l2); split1(v3,h3,l3);
            *(__half2*)(rh + 4*i)     = __halves2half2(h0, h1);
            *(__half2*)(rh + 4*i + 2) = __halves2half2(h2, h3);
            *(__half2*)(rl + 4*i)     = __halves2half2(l0, l1);
            *(__half2*)(rl + 4*i + 2) = __halves2half2(l2, l3);
        }
    }
    __syncthreads();

    // ---- GEMM1: m = silu(m1 @ ew2 + eb2), 3-pass split ----
    u32 Ah[16], Al[16];
#pragma unroll
    for (int ks = 0; ks < 4; ks++) {
        const __half* pa = sA1h + (16 * w + (lane & 15)) * 72 + 16 * ks + 8 * (lane >> 4);
        const __half* pl = sA1l + (16 * w + (lane & 15)) * 72 + 16 * ks + 8 * (lane >> 4);
        ldsm4(&Ah[4 * ks], pa);
        ldsm4(&Al[4 * ks], pl);
    }

    u32 A2h[16], A2l[16];
    int row = 16 * w + (lane >> 2);
#pragma unroll
    for (int ntp = 0; ntp < 4; ntp++) {
        float acc0[4] = {0.f, 0.f, 0.f, 0.f};
        float acc1[4] = {0.f, 0.f, 0.f, 0.f};
#pragma unroll
        for (int ks = 0; ks < 4; ks++) {
            u32 bh[4], bl[4];
            const __half* ph = sW1h + (16 * ks + (lane & 15)) * 72 + 8 * (2 * ntp + (lane >> 4));
            const __half* pl = sW1l + (16 * ks + (lane & 15)) * 72 + 8 * (2 * ntp + (lane >> 4));
            ldsm4t(bh, ph);
            ldsm4t(bl, pl);
            mma16816(acc0, &Ah[4 * ks], bh[0], bh[1]);
            mma16816(acc0, &Ah[4 * ks], bl[0], bl[1]);
            mma16816(acc0, &Al[4 * ks], bh[0], bh[1]);
            mma16816(acc1, &Ah[4 * ks], bh[2], bh[3]);
            mma16816(acc1, &Ah[4 * ks], bl[2], bl[3]);
            mma16816(acc1, &Al[4 * ks], bh[2], bh[3]);
        }
#pragma unroll
        for (int s = 0; s < 2; s++) {
            float* acc = s ? acc1 : acc0;
            int nt = 2 * ntp + s;
            int col = 8 * nt + 2 * (lane & 3);
            float m0 = silu_f(acc[0] + s_eb2[col]);
            float m1 = silu_f(acc[1] + s_eb2[col + 1]);
            float m2 = silu_f(acc[2] + s_eb2[col]);
            float m3 = silu_f(acc[3] + s_eb2[col + 1]);
            if (STORE) {
                int e0 = em0 + row, e1 = em0 + row + 8;
                if (e0 < E) { float2 o; o.x = m0; o.y = m1; *(float2*)(mbuf + (size_t)e0 * 64 + col) = o; }
                if (e1 < E) { float2 o; o.x = m2; o.y = m3; *(float2*)(mbuf + (size_t)e1 * 64 + col) = o; }
            }
            __half h0,h1,h2,h3,l0,l1,l2,l3;
            split1(m0,h0,l0); split1(m1,h1,l1); split1(m2,h2,l2); split1(m3,h3,l3);
            int base = 4 * (nt >> 1) + 2 * (nt & 1);
            A2h[base + 0] = packh2(h0, h1);
            A2h[base + 1] = packh2(h2, h3);
            A2l[base + 0] = packh2(l0, l1);
            A2l[base + 1] = packh2(l2, l3);
        }
    }

    // ---- GEMM2: c1 = silu(m @ cw1 + cb1), 3-pass split; c = c1 . cw2 ----
    float rs0 = 0.f, rs1 = 0.f;
#pragma unroll
    for (int ntp = 0; ntp < 4; ntp++) {
        float acc0[4] = {0.f, 0.f, 0.f, 0.f};
        float acc1[4] = {0.f, 0.f, 0.f, 0.f};
#pragma unroll
        for (int ks = 0; ks < 4; ks++) {
            u32 bh[4], bl[4];
            ldsm4t(bh, sW2h + (16 * ks + (lane & 15)) * 72 + 8 * (2 * ntp + (lane >> 4)));
            ldsm4t(bl, sW2l + (16 * ks + (lane & 15)) * 72 + 8 * (2 * ntp + (lane >> 4)));
            mma16816(acc0, &A2h[4 * ks], bh[0], bh[1]);
            mma16816(acc0, &A2h[4 * ks], bl[0], bl[1]);
            mma16816(acc0, &A2l[4 * ks], bh[0], bh[1]);
            mma16816(acc1, &A2h[4 * ks], bh[2], bh[3]);
            mma16816(acc1, &A2h[4 * ks], bl[2], bl[3]);
            mma16816(acc1, &A2l[4 * ks], bh[2], bh[3]);
        }
#pragma unroll
        for (int s = 0; s < 2; s++) {
            float* acc = s ? acc1 : acc0;
            int col = 8 * (2 * ntp + s) + 2 * (lane & 3);
            rs0 += silu_f(acc[0] + s_cb1[col]) * s_cw2[col]
                 + silu_f(acc[1] + s_cb1[col + 1]) * s_cw2[col + 1];
            rs1 += silu_f(acc[2] + s_cb1[col]) * s_cw2[col]
                 + silu_f(acc[3] + s_cb1[col + 1]) * s_cw2[col + 1];
        }
    }
    rs0 += __shfl_xor_sync(0xffffffffu, rs0, 1);
    rs0 += __shfl_xor_sync(0xffffffffu, rs0, 2);
    rs1 += __shfl_xor_sync(0xffffffffu, rs1, 1);
    rs1 += __shfl_xor_sync(0xffffffffu, rs1, 2);
    if ((lane & 3) == 0) {
        s_cp[16 * w + (lane >> 2)]     = rs0;
        s_cp[16 * w + 8 + (lane >> 2)] = rs1;
    }
    __syncthreads();

    if (t < 128) {
        int e = em0 + t;
        if (e < E) {
            float c = s_cp[t];
            int di = s_di[t];
            float* xp = xacc + (size_t)di * 3;
            red1(xp + 0, c * s_u0[t]);
            red1(xp + 1, c * s_u1[t]);
            red1(xp + 2, c * s_u2[t]);
        }
    }
}

// ------------------- gather -------------------
__global__ void gather_kernel(const float* __restrict__ m, const int* __restrict__ off,
                              const int* __restrict__ eidx, float* __restrict__ hn, int n)
{
    int warp = (blockIdx.x * blockDim.x + threadIdx.x) >> 5;
    int lane = threadIdx.x & 31;
    if (warp >= n) return;
    int b = off[warp], en = off[warp + 1];
    float ax = 0.f, ay = 0.f;
    for (int i = b; i < en; i++) {
        int eid = eidx[i];
        float2 v = ((const float2*)(m + (size_t)eid * 64))[lane];
        ax += v.x; ay += v.y;
    }
    float2 o; o.x = ax; o.y = ay;
    ((float2*)(hn + (size_t)warp * 64))[lane] = o;
}

__global__ void xupd_kernel(const float* __restrict__ x, const float* __restrict__ xacc,
                            float* __restrict__ out, int n3)
{
    int i = blockIdx.x * blockDim.x + threadIdx.x;
    if (i < n3) out[i] = x[i] + xacc[i];
}

// ------------------- launch -------------------
extern "C" void kernel_launch(void* const* d_in, const int* in_sizes, int n_in,
                              void* d_out, int out_size)
{
    const float* h0  = (const float*)d_in[0];
    const float* x0  = (const float*)d_in[1];
    const int*   src = (const int*)d_in[2];
    const int*   dst = (const int*)d_in[3];
    const float* ew1 = (const float*)d_in[4];
    const float* eb1 = (const float*)d_in[5];
    const float* ew2 = (const float*)d_in[6];
    const float* eb2 = (const float*)d_in[7];
    const float* nw1 = (const float*)d_in[8];
    const float* nb1 = (const float*)d_in[9];
    const float* nw2 = (const float*)d_in[10];
    const float* nb2 = (const float*)d_in[11];
    const float* cw1 = (const float*)d_in[12];
    const float* cb1 = (const float*)d_in[13];
    const float* cw2 = (const float*)d_in[14];

    int n = in_sizes[0] / 64;
    int E = in_sizes[2];

    float *P, *hA, *xA, *hacc, *xacc, *tb, *mbuf, *zero;
    int *deg, *off, *woff, *bsum, *bscan, *eidx;
    __half *wh, *wl, *pwh, *pwl, *n1h, *n1l, *n2h, *n2l;
    cudaGetSymbolAddress((void**)&P,    g_P);
    cudaGetSymbolAddress((void**)&hA,   g_hbuf);
    cudaGetSymbolAddress((void**)&xA,   g_xbuf);
    cudaGetSymbolAddress((void**)&hacc, g_hacc);
    cudaGetSymbolAddress((void**)&xacc, g_xacc);
    cudaGetSymbolAddress((void**)&tb,   g_t);
    cudaGetSymbolAddress((void**)&mbuf, g_m);
    cudaGetSymbolAddress((void**)&deg,  g_deg);
    cudaGetSymbolAddress((void**)&off,  g_off);
    cudaGetSymbolAddress((void**)&woff, g_woff);
    cudaGetSymbolAddress((void**)&bsum, g_bsum);
    cudaGetSymbolAddress((void**)&bscan,g_bscan);
    cudaGetSymbolAddress((void**)&eidx, g_eidx);
    cudaGetSymbolAddress((void**)&wh,   g_wh);
    cudaGetSymbolAddress((void**)&wl,   g_wl);
    cudaGetSymbolAddress((void**)&pwh,  g_pwh);
    cudaGetSymbolAddress((void**)&pwl,  g_pwl);
    cudaGetSymbolAddress((void**)&n1h,  g_n1h);
    cudaGetSymbolAddress((void**)&n1l,  g_n1l);
    cudaGetSymbolAddress((void**)&n2h,  g_n2h);
    cudaGetSymbolAddress((void**)&n2l,  g_n2l);
    cudaGetSymbolAddress((void**)&zero, g_zero);

    float* hb[2] = { hA, hA + (size_t)NN * 64 };
    float* xb[2] = { xA, xA + (size_t)NN * 3 };

    const int smE  = (4 * HW + 2 * HA) * 2 + 960 * 4;
    const int smP2 = (2 * 64 * 72 + 2 * 64 * 136) * 2 + 128 * 4;       // K=64,N=128
    const int smN1 = (2 * 64 * 136 + 2 * 128 * 72) * 2 + 64 * 4;       // K=128,N=64
    const int smN2 = (2 * 64 * 72 + 2 * 64 * 72) * 2 + 64 * 4;         // K=64,N=64
    cudaFuncSetAttribute(edge_kernel<true>,  cudaFuncAttributeMaxDynamicSharedMemorySize, smE);
    cudaFuncSetAttribute(edge_kernel<false>, cudaFuncAttributeMaxDynamicSharedMemorySize, smE);
    cudaFuncSetAttribute(tgemm_kernel<64, 128, false>, cudaFuncAttributeMaxDynamicSharedMemorySize, smP2);
    cudaFuncSetAttribute(tgemm_kernel<128, 64, true>,  cudaFuncAttributeMaxDynamicSharedMemorySize, smN1);
    cudaFuncSetAttribute(tgemm_kernel<64, 64, false>,  cudaFuncAttributeMaxDynamicSharedMemorySize, smN2);

    int nb_rows = (n + 63) / 64;
    int eb_blocks = (E + 127) / 128;
    int scan_nb = (n + 511) / 512;

    deg_zero_kernel<<<(n * 3 + 255) / 256, 256>>>(deg, xacc, n);
    wsplit_kernel<<<(DEPTH * 2 * 4096 + 255) / 256, 256>>>(ew2, cw1, wh, wl);
    wsplit2_kernel<<<(DEPTH * 8192 + 255) / 256, 256>>>(ew1, nw1, nw2,
                                                        pwh, pwl, n1h, n1l, n2h, n2l);

    for (int d = 0; d < DEPTH; d++) {
        const float* hc = d ? hb[(d - 1) & 1] : h0;
        const float* xc = d ? xb[(d - 1) & 1] : x0;
        float* xo = (d == DEPTH - 1) ? (float*)d_out : xb[d & 1];

        if (d) zerox_kernel<<<(n * 3 + 255) / 256, 256>>>(xacc, n * 3);

        tgemm_kernel<64, 128, false><<<nb_rows, 128, smP2>>>(
            hc, hc, pwh + (size_t)d * 8192, pwl + (size_t)d * 8192, zero, P, n);

        const __half* w1h = wh + (size_t)(2 * d) * 4096;
        const __half* w1l = wl + (size_t)(2 * d) * 4096;
        const __half* w2h = wh + (size_t)(2 * d + 1) * 4096;
        const __half* w2l = wl + (size_t)(2 * d + 1) * 4096;
        const float* wrp = ew1 + (size_t)d * 129 * 64 + 128 * 64;

        if (d < DEPTH - 1) {
            edge_kernel<true><<<eb_blocks, 256, smE>>>(
                src, dst, xc, P, wrp, eb1 + d * 64,
                w1h, w1l, eb2 + d * 64, w2h, w2l,
                cb1 + d * 64, cw2 + d * 64, mbuf, xacc, E);

            if (d == 0) {
                deg_count_kernel<<<(E + 255) / 256, 256>>>(dst, deg, E);
                scan_blocks_kernel<<<scan_nb, 512>>>(deg, off, bsum, n);
                scan_bsums_kernel<<<1, 32>>>(bsum, bscan, scan_nb);
                scan_add_kernel<<<(n + 255) / 256, 256>>>(off, bscan, woff, n, E);
                fill_eidx_kernel<<<(E + 255) / 256, 256>>>(dst, woff, eidx, E);
            }

            gather_kernel<<<(n * 32 + 255) / 256, 256>>>(mbuf, off, eidx, hacc, n);

            tgemm_kernel<128, 64, true><<<nb_rows, 128, smN1>>>(
                hc, hacc, n1h + (size_t)d * 8192, n1l + (size_t)d * 8192,
                nb1 + d * 64, tb, n);
            tgemm_kernel<64, 64, false><<<nb_rows, 128, smN2>>>(
                tb, tb, n2h + (size_t)d * 4096, n2l + (size_t)d * 4096,
                nb2 + d * 64, hb[d & 1], n);
        } else {
            edge_kernel<false><<<eb_blocks, 256, smE>>>(
                src, dst, xc, P, wrp, eb1 + d * 64,
                w1h, w1l, eb2 + d * 64, w2h, w2l,
                cb1 + d * 64, cw2 + d * 64, mbuf, xacc, E);
        }

        xupd_kernel<<<(n * 3 + 255) / 256, 256>>>(xc, xacc, xo, n * 3);
    }
}